// round 1
// baseline (speedup 1.0000x reference)
#include <cuda_runtime.h>
#include <math.h>

#define B_N 4096
#define F_N 2048
#define M_N 14
#define C_N 100
#define K_N 16384
#define PAD 129

__device__ float g_Whi[B_N * 128];
__device__ float g_Wlo[B_N * 128];
__device__ float g_Le[B_N * M_N];
__device__ float g_pi[C_N * K_N];
__device__ float g_piL[C_N * K_N];
__device__ double g_acc;

__global__ void k_init() { g_acc = 0.0; }

// ---------------------------------------------------------------------------
// K1: le[b,j] = alpha0[j] + sum_col x[b,col]*alpha[j,col]
//     + per-row softplus sums (EIV), + whi[b,0:128], wlo[b,0:128]
// 128 blocks x 256 threads; 32 rows/block; alpha staged in smem.
// ---------------------------------------------------------------------------
__global__ void k_le(const float* __restrict__ x,
                     const float* __restrict__ alpha,
                     const float* __restrict__ alpha0) {
    extern __shared__ float sm[];
    float* salpha = sm;                    // 14*2048
    float* sle    = sm + M_N * F_N;        // 32*14
    float* sShi   = sle + 32 * M_N;        // 32
    float* sSlo   = sShi + 32;             // 32

    int tid = threadIdx.x;
    for (int idx = tid; idx < M_N * F_N; idx += 256) salpha[idx] = alpha[idx];
    __syncthreads();

    int p  = tid >> 4;        // 0..15 -> row pair
    int cg = tid & 15;        // column group
    int r0 = blockIdx.x * 32 + p * 2;
    int r1 = r0 + 1;

    float acc0[M_N], acc1[M_N];
#pragma unroll
    for (int j = 0; j < M_N; j++) { acc0[j] = 0.f; acc1[j] = 0.f; }

    const float* x0 = x + (size_t)r0 * F_N;
    const float* x1 = x + (size_t)r1 * F_N;

#pragma unroll 4
    for (int m = 0; m < 128; m++) {
        int col = cg + (m << 4);
        float xa = x0[col];
        float xb = x1[col];
#pragma unroll
        for (int j = 0; j < M_N; j++) {
            float a = salpha[j * F_N + col];
            acc0[j] = fmaf(xa, a, acc0[j]);
            acc1[j] = fmaf(xb, a, acc1[j]);
        }
    }

    // reduce over the 16 column groups (lanes 0..15 / 16..31 are separate pairs)
#pragma unroll
    for (int j = 0; j < M_N; j++) {
#pragma unroll
        for (int m = 8; m >= 1; m >>= 1) {
            acc0[j] += __shfl_xor_sync(0xffffffffu, acc0[j], m);
            acc1[j] += __shfl_xor_sync(0xffffffffu, acc1[j], m);
        }
    }

    if (cg == 0) {
        float Shi0 = 0.f, Slo0 = 0.f, Shi1 = 0.f, Slo1 = 0.f;
        int lr0 = p * 2, lr1 = p * 2 + 1;
#pragma unroll
        for (int j = 0; j < M_N; j++) {
            float l0 = alpha0[j] + acc0[j];
            float l1 = alpha0[j] + acc1[j];
            sle[lr0 * M_N + j] = l0;
            sle[lr1 * M_N + j] = l1;
            g_Le[r0 * M_N + j] = l0;
            g_Le[r1 * M_N + j] = l1;
            float sp0 = fmaxf(l0, 0.f) + log1pf(expf(-fabsf(l0)));
            float sp1 = fmaxf(l1, 0.f) + log1pf(expf(-fabsf(l1)));
            if (j < 7) { Shi0 += sp0; Shi1 += sp1; }
            else       { Slo0 += sp0; Slo1 += sp1; }
        }
        sShi[lr0] = Shi0; sSlo[lr0] = Slo0;
        sShi[lr1] = Shi1; sSlo[lr1] = Slo1;
        atomicAdd(&g_acc, -(double)(Shi0 + Slo0 + Shi1 + Slo1));  // -EIV
    }
    __syncthreads();

    // whi/wlo: 32 rows x 256 values
    for (int v = tid; v < 32 * 256; v += 256) {
        int row = v >> 8, rem = v & 255;
        int half = rem >> 7, idx = rem & 127;
        int b = blockIdx.x * 32 + row;
        if (half == 0) {
            float d = 0.f;
#pragma unroll
            for (int j = 0; j < 7; j++)
                d = fmaf((float)((idx >> (6 - j)) & 1), sle[row * M_N + j], d);
            g_Whi[b * 128 + idx] = expf(d - sShi[row]);
        } else {
            float d = 0.f;
#pragma unroll
            for (int j = 7; j < 14; j++)
                d = fmaf((float)((idx >> (13 - j)) & 1), sle[row * M_N + j], d);
            g_Wlo[b * 128 + idx] = expf(d - sSlo[row]);
        }
    }
}

// ---------------------------------------------------------------------------
// K2: per code k: linear_pi[c,k], softmax over classes, L_k = logsumexp.
// Writes g_pi[c,k], g_piL[c,k] = pi*L. One thread per k, 3 passes.
// ---------------------------------------------------------------------------
__global__ void k_pi(const float* __restrict__ beta0,
                     const float* __restrict__ beta) {
    __shared__ float sb[C_N * M_N];
    __shared__ float sb0[C_N];
    int tid = threadIdx.x;
    for (int i = tid; i < C_N * M_N; i += 256) sb[i] = beta[i];
    for (int i = tid; i < C_N; i += 256) sb0[i] = beta0[i];
    __syncthreads();

    int k = blockIdx.x * 256 + tid;
    float sg[M_N];
#pragma unroll
    for (int j = 0; j < M_N; j++)
        sg[j] = ((k >> (13 - j)) & 1) ? 1.f : -1.f;

    float mx = -1e30f;
    for (int c = 0; c < C_N; c++) {
        float lp = sb0[c];
#pragma unroll
        for (int j = 0; j < M_N; j++) lp = fmaf(sg[j], sb[c * M_N + j], lp);
        mx = fmaxf(mx, lp);
    }
    float s = 0.f;
    for (int c = 0; c < C_N; c++) {
        float lp = sb0[c];
#pragma unroll
        for (int j = 0; j < M_N; j++) lp = fmaf(sg[j], sb[c * M_N + j], lp);
        s += expf(lp - mx);
    }
    float L = mx + logf(s);
    float inv = 1.f / s;
    for (int c = 0; c < C_N; c++) {
        float lp = sb0[c];
#pragma unroll
        for (int j = 0; j < M_N; j++) lp = fmaf(sg[j], sb[c * M_N + j], lp);
        float pv = expf(lp - mx) * inv;
        g_pi[c * K_N + k]  = pv;
        g_piL[c * K_N + k] = pv * L;
    }
}

// ---------------------------------------------------------------------------
// K4: one block per class. Pi_c and PiL_c resident in smem.
// For each group of 8 samples of this class:
//   V = Pi * wlo, R = PiL * wlo, U = Pi^T * whi
//   denom  = whi.V ; num_hi_j = sum_{h bit j} whi[h]V[h]
//   num_lo_j = sum_{l bit j} wlo[l]U[l] ; eii = whi.R
// Then the per-sample scalar contribution (EI - EII + EIII) -> double atomic.
// ---------------------------------------------------------------------------
__global__ void k_main(const int* __restrict__ y,
                       const float* __restrict__ beta0,
                       const float* __restrict__ beta) {
    extern __shared__ float sm[];
    float* sPi  = sm;                    // 128*PAD
    float* sPiL = sPi + 128 * PAD;       // 128*PAD
    float* sWhi = sPiL + 128 * PAD;      // 8*128
    float* sWlo = sWhi + 1024;           // 8*128
    float* sV   = sWlo + 1024;           // 8*128
    float* sR   = sV + 1024;             // 8*128
    float* sU   = sR + 1024;             // 8*128
    int*   slist = (int*)(sU + 1024);    // 4096
    __shared__ int s_cnt;

    int tid = threadIdx.x;
    int c = blockIdx.x;
    if (tid == 0) s_cnt = 0;
    __syncthreads();
    for (int i = tid; i < B_N; i += 256)
        if (y[i] == c) slist[atomicAdd(&s_cnt, 1)] = i;
    __syncthreads();
    int n = s_cnt;
    if (n == 0) return;

    for (int idx = tid; idx < K_N; idx += 256) {
        int h = idx >> 7, l = idx & 127;
        sPi[h * PAD + l]  = g_pi[c * K_N + idx];
        sPiL[h * PAD + l] = g_piL[c * K_N + idx];
    }
    __syncthreads();

    for (int g0 = 0; g0 < n; g0 += 8) {
        // stage whi/wlo for up to 8 samples (zero-fill the tail)
        for (int v = tid; v < 2048; v += 256) {
            int s = v >> 8, rem = v & 255, half = rem >> 7, idx = rem & 127;
            float val = 0.f;
            if (g0 + s < n) {
                int b = slist[g0 + s];
                val = half ? g_Wlo[b * 128 + idx] : g_Whi[b * 128 + idx];
            }
            if (half == 0) sWhi[s * 128 + idx] = val;
            else           sWlo[s * 128 + idx] = val;
        }
        __syncthreads();

        // V (threads 0..127) and R (threads 128..255)
        {
            int h = tid & 127;
            const float* mat = (tid < 128) ? sPi : sPiL;
            float acc[8];
#pragma unroll
            for (int s = 0; s < 8; s++) acc[s] = 0.f;
            for (int l = 0; l < 128; l++) {
                float pv = mat[h * PAD + l];
#pragma unroll
                for (int s = 0; s < 8; s++)
                    acc[s] = fmaf(pv, sWlo[s * 128 + l], acc[s]);
            }
            float* out = (tid < 128) ? sV : sR;
#pragma unroll
            for (int s = 0; s < 8; s++) out[s * 128 + h] = acc[s];
        }
        // U: all 256 threads, each does 4 samples for one column l
        {
            int l = tid & 127;
            int sbase = (tid >> 7) * 4;
            float acc[4];
#pragma unroll
            for (int q = 0; q < 4; q++) acc[q] = 0.f;
            for (int h = 0; h < 128; h++) {
                float pv = sPi[h * PAD + l];
#pragma unroll
                for (int q = 0; q < 4; q++)
                    acc[q] = fmaf(pv, sWhi[(sbase + q) * 128 + h], acc[q]);
            }
#pragma unroll
            for (int q = 0; q < 4; q++) sU[(sbase + q) * 128 + l] = acc[q];
        }
        __syncthreads();

        // finalize: warp w handles sample w
        int w = tid >> 5, lane = tid & 31;
        if (g0 + w < n) {
            int s = w;
            float dacc = 0.f, eacc = 0.f;
            float nh[7] = {0, 0, 0, 0, 0, 0, 0};
            float nl[7] = {0, 0, 0, 0, 0, 0, 0};
#pragma unroll
            for (int q = 0; q < 4; q++) {
                int h = lane * 4 + q;   // serves both the h index and the l index
                float whv = sWhi[s * 128 + h];
                float wv = whv * sV[s * 128 + h];
                dacc += wv;
                eacc = fmaf(whv, sR[s * 128 + h], eacc);
                float wu = sWlo[s * 128 + h] * sU[s * 128 + h];
#pragma unroll
                for (int j = 0; j < 7; j++) {
                    float bit = (float)((h >> (6 - j)) & 1);
                    nh[j] = fmaf(bit, wv, nh[j]);
                    nl[j] = fmaf(bit, wu, nl[j]);
                }
            }
#pragma unroll
            for (int m = 16; m >= 1; m >>= 1) {
                dacc += __shfl_xor_sync(0xffffffffu, dacc, m);
                eacc += __shfl_xor_sync(0xffffffffu, eacc, m);
#pragma unroll
                for (int j = 0; j < 7; j++) {
                    nh[j] += __shfl_xor_sync(0xffffffffu, nh[j], m);
                    nl[j] += __shfl_xor_sync(0xffffffffu, nl[j], m);
                }
            }
            if (lane == 0) {
                int b = slist[g0 + s];
                float inv = 1.f / dacc;
                float contrib = beta0[c] - eacc * inv;  // EI const part - EII
#pragma unroll
                for (int j = 0; j < 7; j++) {
                    float Ez = nh[j] * inv;
                    contrib += (2.f * Ez - 1.f) * beta[c * M_N + j]
                             + Ez * g_Le[b * M_N + j];
                }
#pragma unroll
                for (int j = 7; j < 14; j++) {
                    float Ez = nl[j - 7] * inv;
                    contrib += (2.f * Ez - 1.f) * beta[c * M_N + j]
                             + Ez * g_Le[b * M_N + j];
                }
                atomicAdd(&g_acc, (double)contrib);
            }
        }
        __syncthreads();
    }
}

__global__ void k_fin(float* out) { out[0] = (float)g_acc; }

extern "C" void kernel_launch(void* const* d_in, const int* in_sizes, int n_in,
                              void* d_out, int out_size) {
    const float* x   = (const float*)d_in[0];
    const int*   y   = (const int*)d_in[1];
    const float* a0  = (const float*)d_in[2];
    const float* al  = (const float*)d_in[3];
    const float* b0  = (const float*)d_in[4];
    const float* be  = (const float*)d_in[5];
    float* out = (float*)d_out;

    const int SMEM1 = (M_N * F_N + 32 * M_N + 64) * 4;             // ~116.8 KB
    const int SMEM4 = (2 * 128 * PAD + 5 * 1024) * 4 + B_N * 4;    // ~169 KB

    cudaFuncSetAttribute(k_le, cudaFuncAttributeMaxDynamicSharedMemorySize, SMEM1);
    cudaFuncSetAttribute(k_main, cudaFuncAttributeMaxDynamicSharedMemorySize, SMEM4);

    k_init<<<1, 1>>>();
    k_le<<<128, 256, SMEM1>>>(x, al, a0);
    k_pi<<<K_N / 256, 256>>>(b0, be);
    k_main<<<C_N, 256, SMEM4>>>(y, b0, be);
    k_fin<<<1, 1>>>(out);
}

// round 2
// speedup vs baseline: 2.0200x; 2.0200x over previous
#include <cuda_runtime.h>
#include <math.h>

#define B_N 4096
#define F_N 2048
#define M_N 14
#define C_N 100
#define K_N 16384
#define PAD 129
#define MAXN 128          // max samples per class supported
#define GRP 16            // samples per k_main block
#define NCHUNK (MAXN / GRP)

__device__ float g_Whi[B_N * 128];
__device__ float g_Wlo[B_N * 128];
__device__ float g_Le[B_N * M_N];
__device__ float g_pi[C_N * K_N];
__device__ float g_piL[C_N * K_N];
__device__ int   g_list[C_N * MAXN];
__device__ int   g_cnt[C_N];
__device__ double g_acc;

__global__ void k_init() { g_acc = 0.0; }

// ---------------------------------------------------------------------------
// K1: le[b,j] = alpha0[j] + x[b,:] . alpha[j,:]; softplus sums (EIV); whi/wlo.
// ---------------------------------------------------------------------------
__global__ void k_le(const float* __restrict__ x,
                     const float* __restrict__ alpha,
                     const float* __restrict__ alpha0) {
    extern __shared__ float sm[];
    float* salpha = sm;                    // 14*2048
    float* sle    = sm + M_N * F_N;        // 32*14
    float* sShi   = sle + 32 * M_N;        // 32
    float* sSlo   = sShi + 32;             // 32

    int tid = threadIdx.x;
    for (int idx = tid; idx < M_N * F_N; idx += 256) salpha[idx] = alpha[idx];
    __syncthreads();

    int p  = tid >> 4;
    int cg = tid & 15;
    int r0 = blockIdx.x * 32 + p * 2;
    int r1 = r0 + 1;

    float acc0[M_N], acc1[M_N];
#pragma unroll
    for (int j = 0; j < M_N; j++) { acc0[j] = 0.f; acc1[j] = 0.f; }

    const float* x0 = x + (size_t)r0 * F_N;
    const float* x1 = x + (size_t)r1 * F_N;

#pragma unroll 4
    for (int m = 0; m < 128; m++) {
        int col = cg + (m << 4);
        float xa = x0[col];
        float xb = x1[col];
#pragma unroll
        for (int j = 0; j < M_N; j++) {
            float a = salpha[j * F_N + col];
            acc0[j] = fmaf(xa, a, acc0[j]);
            acc1[j] = fmaf(xb, a, acc1[j]);
        }
    }

#pragma unroll
    for (int j = 0; j < M_N; j++) {
#pragma unroll
        for (int m = 8; m >= 1; m >>= 1) {
            acc0[j] += __shfl_xor_sync(0xffffffffu, acc0[j], m);
            acc1[j] += __shfl_xor_sync(0xffffffffu, acc1[j], m);
        }
    }

    if (cg == 0) {
        float Shi0 = 0.f, Slo0 = 0.f, Shi1 = 0.f, Slo1 = 0.f;
        int lr0 = p * 2, lr1 = p * 2 + 1;
#pragma unroll
        for (int j = 0; j < M_N; j++) {
            float l0 = alpha0[j] + acc0[j];
            float l1 = alpha0[j] + acc1[j];
            sle[lr0 * M_N + j] = l0;
            sle[lr1 * M_N + j] = l1;
            g_Le[r0 * M_N + j] = l0;
            g_Le[r1 * M_N + j] = l1;
            float sp0 = fmaxf(l0, 0.f) + log1pf(expf(-fabsf(l0)));
            float sp1 = fmaxf(l1, 0.f) + log1pf(expf(-fabsf(l1)));
            if (j < 7) { Shi0 += sp0; Shi1 += sp1; }
            else       { Slo0 += sp0; Slo1 += sp1; }
        }
        sShi[lr0] = Shi0; sSlo[lr0] = Slo0;
        sShi[lr1] = Shi1; sSlo[lr1] = Slo1;
        atomicAdd(&g_acc, -(double)(Shi0 + Slo0 + Shi1 + Slo1));  // -EIV
    }
    __syncthreads();

    for (int v = tid; v < 32 * 256; v += 256) {
        int row = v >> 8, rem = v & 255;
        int half = rem >> 7, idx = rem & 127;
        int b = blockIdx.x * 32 + row;
        if (half == 0) {
            float d = 0.f;
#pragma unroll
            for (int j = 0; j < 7; j++)
                d = fmaf((float)((idx >> (6 - j)) & 1), sle[row * M_N + j], d);
            g_Whi[b * 128 + idx] = expf(d - sShi[row]);
        } else {
            float d = 0.f;
#pragma unroll
            for (int j = 7; j < 14; j++)
                d = fmaf((float)((idx >> (13 - j)) & 1), sle[row * M_N + j], d);
            g_Wlo[b * 128 + idx] = expf(d - sSlo[row]);
        }
    }
}

// ---------------------------------------------------------------------------
// K2: per code k: softmax over classes + logsumexp tables.
// ---------------------------------------------------------------------------
__global__ void k_pi(const float* __restrict__ beta0,
                     const float* __restrict__ beta) {
    __shared__ float sb[C_N * M_N];
    __shared__ float sb0[C_N];
    int tid = threadIdx.x;
    for (int i = tid; i < C_N * M_N; i += 256) sb[i] = beta[i];
    for (int i = tid; i < C_N; i += 256) sb0[i] = beta0[i];
    __syncthreads();

    int k = blockIdx.x * 256 + tid;
    float sg[M_N];
#pragma unroll
    for (int j = 0; j < M_N; j++)
        sg[j] = ((k >> (13 - j)) & 1) ? 1.f : -1.f;

    float mx = -1e30f;
    for (int c = 0; c < C_N; c++) {
        float lp = sb0[c];
#pragma unroll
        for (int j = 0; j < M_N; j++) lp = fmaf(sg[j], sb[c * M_N + j], lp);
        mx = fmaxf(mx, lp);
    }
    float s = 0.f;
    for (int c = 0; c < C_N; c++) {
        float lp = sb0[c];
#pragma unroll
        for (int j = 0; j < M_N; j++) lp = fmaf(sg[j], sb[c * M_N + j], lp);
        s += expf(lp - mx);
    }
    float L = mx + logf(s);
    float inv = 1.f / s;
    for (int c = 0; c < C_N; c++) {
        float lp = sb0[c];
#pragma unroll
        for (int j = 0; j < M_N; j++) lp = fmaf(sg[j], sb[c * M_N + j], lp);
        float pv = expf(lp - mx) * inv;
        g_pi[c * K_N + k]  = pv;
        g_piL[c * K_N + k] = pv * L;
    }
}

// ---------------------------------------------------------------------------
// K3: deterministic CSR: per-class ordered sample lists via ballot compaction.
// One block (256 thr) per class.
// ---------------------------------------------------------------------------
__global__ void k_csr(const int* __restrict__ y) {
    int c = blockIdx.x;
    int tid = threadIdx.x, lane = tid & 31, wid = tid >> 5;
    __shared__ int wcnt[8];
    __shared__ int sbase;
    if (tid == 0) sbase = 0;
    __syncthreads();
    for (int r = 0; r < B_N / 256; r++) {
        int i = r * 256 + tid;
        bool m = (y[i] == c);
        unsigned bal = __ballot_sync(0xffffffffu, m);
        if (lane == 0) wcnt[wid] = __popc(bal);
        __syncthreads();
        int woff = sbase;
        for (int w = 0; w < wid; w++) woff += wcnt[w];
        int pos = woff + __popc(bal & ((1u << lane) - 1));
        if (m && pos < MAXN) g_list[c * MAXN + pos] = i;
        __syncthreads();
        if (tid == 0) {
            int t = 0;
            for (int w = 0; w < 8; w++) t += wcnt[w];
            sbase += t;
        }
        __syncthreads();
    }
    if (tid == 0) g_cnt[c] = (sbase < MAXN) ? sbase : MAXN;
}

// ---------------------------------------------------------------------------
// K4: grid = C_N * NCHUNK blocks, 512 threads. Block (c, chunk) handles
// samples [chunk*GRP, chunk*GRP+GRP) of class c.
//   fused V/R: V = Pi*wlo, R = PiL*wlo   then U = Pi^T*whi
//   finalize per sample -> double atomic.
// ---------------------------------------------------------------------------
__global__ void __launch_bounds__(512)
k_main(const float* __restrict__ beta0,
       const float* __restrict__ beta) {
    extern __shared__ float sm[];
    float* sPi   = sm;                       // 128*PAD
    float* sPiL  = sPi + 128 * PAD;          // 128*PAD
    float* sWloT = sPiL + 128 * PAD;         // 128*GRP  (l-major)
    float* sWhiT = sWloT + 128 * GRP;        // 128*GRP  (h-major)
    float* sWloS = sWhiT + 128 * GRP;        // GRP*128  (s-major)
    float* sWhiS = sWloS + GRP * 128;        // GRP*128
    float* sV    = sWhiS + GRP * 128;        // GRP*128
    float* sR    = sV + GRP * 128;           // GRP*128
    float* sU    = sR + GRP * 128;           // GRP*128

    int tid = threadIdx.x;
    int c = blockIdx.x / NCHUNK;
    int chunk = blockIdx.x % NCHUNK;
    int n = g_cnt[c];
    int start = chunk * GRP;
    if (start >= n) return;

    // load Pi / PiL tiles (padded layout)
    const float* gp  = g_pi  + (size_t)c * K_N;
    const float* gpl = g_piL + (size_t)c * K_N;
    for (int idx = tid; idx < K_N; idx += 512) {
        int h = idx >> 7, l = idx & 127;
        sPi[h * PAD + l]  = gp[idx];
        sPiL[h * PAD + l] = gpl[idx];
    }

    // stage whi/wlo in both layouts (zero pad past n)
    for (int v = tid; v < GRP * 128; v += 512) {
        int s = v >> 7, idx = v & 127;
        float vh = 0.f, vl = 0.f;
        if (start + s < n) {
            int b = g_list[c * MAXN + start + s];
            vh = g_Whi[b * 128 + idx];
            vl = g_Wlo[b * 128 + idx];
        }
        sWhiS[s * 128 + idx] = vh;
        sWloS[s * 128 + idx] = vl;
        sWhiT[idx * GRP + s] = vh;
        sWloT[idx * GRP + s] = vl;
    }
    __syncthreads();

    // fused V/R pass: thread (h, sg) computes V,R for 4 samples
    {
        int h = tid & 127;
        int sg = tid >> 7;      // 0..3
        float accV[4] = {0, 0, 0, 0};
        float accR[4] = {0, 0, 0, 0};
        const float* rowPi  = sPi + h * PAD;
        const float* rowPiL = sPiL + h * PAD;
#pragma unroll 4
        for (int l = 0; l < 128; l++) {
            float pv = rowPi[l];
            float pr = rowPiL[l];
            float4 w = *(const float4*)&sWloT[l * GRP + sg * 4];
            accV[0] = fmaf(pv, w.x, accV[0]);
            accV[1] = fmaf(pv, w.y, accV[1]);
            accV[2] = fmaf(pv, w.z, accV[2]);
            accV[3] = fmaf(pv, w.w, accV[3]);
            accR[0] = fmaf(pr, w.x, accR[0]);
            accR[1] = fmaf(pr, w.y, accR[1]);
            accR[2] = fmaf(pr, w.z, accR[2]);
            accR[3] = fmaf(pr, w.w, accR[3]);
        }
#pragma unroll
        for (int q = 0; q < 4; q++) {
            sV[(sg * 4 + q) * 128 + h] = accV[q];
            sR[(sg * 4 + q) * 128 + h] = accR[q];
        }
    }
    // U pass: thread (l, sg): U[s][l] = sum_h Pi[h][l]*whi[s][h]
    {
        int l = tid & 127;
        int sg = tid >> 7;
        float acc[4] = {0, 0, 0, 0};
#pragma unroll 4
        for (int h = 0; h < 128; h++) {
            float pv = sPi[h * PAD + l];
            float4 w = *(const float4*)&sWhiT[h * GRP + sg * 4];
            acc[0] = fmaf(pv, w.x, acc[0]);
            acc[1] = fmaf(pv, w.y, acc[1]);
            acc[2] = fmaf(pv, w.z, acc[2]);
            acc[3] = fmaf(pv, w.w, acc[3]);
        }
#pragma unroll
        for (int q = 0; q < 4; q++)
            sU[(sg * 4 + q) * 128 + l] = acc[q];
    }
    __syncthreads();

    // finalize: warp w handles sample w
    int w = tid >> 5, lane = tid & 31;
    if (start + w < n) {
        float dacc = 0.f, eacc = 0.f;
        float nh[7] = {0, 0, 0, 0, 0, 0, 0};
        float nl[7] = {0, 0, 0, 0, 0, 0, 0};
        float4 whi4 = *(const float4*)&sWhiS[w * 128 + lane * 4];
        float4 wlo4 = *(const float4*)&sWloS[w * 128 + lane * 4];
        float4 V4   = *(const float4*)&sV[w * 128 + lane * 4];
        float4 R4   = *(const float4*)&sR[w * 128 + lane * 4];
        float4 U4   = *(const float4*)&sU[w * 128 + lane * 4];
        const float* whiA = (const float*)&whi4;
        const float* wloA = (const float*)&wlo4;
        const float* VA = (const float*)&V4;
        const float* RA = (const float*)&R4;
        const float* UA = (const float*)&U4;
#pragma unroll
        for (int q = 0; q < 4; q++) {
            int h = lane * 4 + q;
            float wv = whiA[q] * VA[q];
            dacc += wv;
            eacc = fmaf(whiA[q], RA[q], eacc);
            float wu = wloA[q] * UA[q];
#pragma unroll
            for (int j = 0; j < 7; j++) {
                float bit = (float)((h >> (6 - j)) & 1);
                nh[j] = fmaf(bit, wv, nh[j]);
                nl[j] = fmaf(bit, wu, nl[j]);
            }
        }
#pragma unroll
        for (int m = 16; m >= 1; m >>= 1) {
            dacc += __shfl_xor_sync(0xffffffffu, dacc, m);
            eacc += __shfl_xor_sync(0xffffffffu, eacc, m);
#pragma unroll
            for (int j = 0; j < 7; j++) {
                nh[j] += __shfl_xor_sync(0xffffffffu, nh[j], m);
                nl[j] += __shfl_xor_sync(0xffffffffu, nl[j], m);
            }
        }
        if (lane == 0) {
            int b = g_list[c * MAXN + start + w];
            float inv = 1.f / dacc;
            float contrib = beta0[c] - eacc * inv;
#pragma unroll
            for (int j = 0; j < 7; j++) {
                float Ez = nh[j] * inv;
                contrib += (2.f * Ez - 1.f) * beta[c * M_N + j]
                         + Ez * g_Le[b * M_N + j];
            }
#pragma unroll
            for (int j = 7; j < 14; j++) {
                float Ez = nl[j - 7] * inv;
                contrib += (2.f * Ez - 1.f) * beta[c * M_N + j]
                         + Ez * g_Le[b * M_N + j];
            }
            atomicAdd(&g_acc, (double)contrib);
        }
    }
}

__global__ void k_fin(float* out) { out[0] = (float)g_acc; }

extern "C" void kernel_launch(void* const* d_in, const int* in_sizes, int n_in,
                              void* d_out, int out_size) {
    const float* x   = (const float*)d_in[0];
    const int*   y   = (const int*)d_in[1];
    const float* a0  = (const float*)d_in[2];
    const float* al  = (const float*)d_in[3];
    const float* b0  = (const float*)d_in[4];
    const float* be  = (const float*)d_in[5];
    float* out = (float*)d_out;

    const int SMEM1 = (M_N * F_N + 32 * M_N + 64) * 4;
    const int SMEM4 = (2 * 128 * PAD + 2 * 128 * GRP + 5 * GRP * 128) * 4;

    cudaFuncSetAttribute(k_le, cudaFuncAttributeMaxDynamicSharedMemorySize, SMEM1);
    cudaFuncSetAttribute(k_main, cudaFuncAttributeMaxDynamicSharedMemorySize, SMEM4);

    k_init<<<1, 1>>>();
    k_le<<<128, 256, SMEM1>>>(x, al, a0);
    k_pi<<<K_N / 256, 256>>>(b0, be);
    k_csr<<<C_N, 256>>>(y);
    k_main<<<C_N * NCHUNK, 512, SMEM4>>>(b0, be);
    k_fin<<<1, 1>>>(out);
}

// round 3
// speedup vs baseline: 2.3852x; 1.1808x over previous
#include <cuda_runtime.h>
#include <math.h>

#define B_N 4096
#define F_N 2048
#define M_N 14
#define C_N 100
#define K_N 16384
#define PAD 129
#define GRP 16

__device__ float g_Whi[B_N * 128];   // whi' = whi * Ehi[y_b]
__device__ float g_Wlo[B_N * 128];   // wlo' = wlo * Elo[y_b]
__device__ float g_Le[B_N * M_N];
__device__ float g_Ehi[C_N * 128];
__device__ float g_Elo[C_N * 128];
__device__ float g_Dinv[128 * 128];   // 1/D
__device__ float g_DinvL[128 * 128];  // log(D)/D
__device__ double g_acc;

__global__ void k_init() { g_acc = 0.0; }

// ---------------------------------------------------------------------------
// Ehi[c,h] = exp(beta0[c] + sum_{j<7} sign_j(h) beta[c,j])
// Elo[c,l] = exp(sum_{j<7} sign_j(l) beta[c,7+j])
// ---------------------------------------------------------------------------
__global__ void k_ehilo(const float* __restrict__ beta0,
                        const float* __restrict__ beta) {
    int c = blockIdx.x, t = threadIdx.x;
    if (t < 128) {
        int h = t;
        float v = beta0[c];
#pragma unroll
        for (int j = 0; j < 7; j++)
            v += (((h >> (6 - j)) & 1) ? 1.f : -1.f) * beta[c * M_N + j];
        g_Ehi[c * 128 + h] = expf(v);
    } else {
        int l = t - 128;
        float v = 0.f;
#pragma unroll
        for (int j = 0; j < 7; j++)
            v += (((l >> (6 - j)) & 1) ? 1.f : -1.f) * beta[c * M_N + 7 + j];
        g_Elo[c * 128 + l] = expf(v);
    }
}

// ---------------------------------------------------------------------------
// D[h,l] = sum_c Ehi[c,h]*Elo[c,l];  Dinv = 1/D;  DinvL = log(D)/D
// grid 128 (h), block 128 (l)
// ---------------------------------------------------------------------------
__global__ void k_D() {
    int h = blockIdx.x, l = threadIdx.x;
    float d = 0.f;
#pragma unroll 4
    for (int c = 0; c < C_N; c++)
        d = fmaf(__ldg(&g_Ehi[c * 128 + h]), __ldg(&g_Elo[c * 128 + l]), d);
    float inv = 1.f / d;
    g_Dinv[h * 128 + l] = inv;
    g_DinvL[h * 128 + l] = logf(d) * inv;
}

// ---------------------------------------------------------------------------
// K_le: le = alpha0 + x @ alpha^T ; EIV; whi'/wlo' via sigmoid products.
// 128 blocks x 256 threads; 32 rows/block.
// ---------------------------------------------------------------------------
__global__ void k_le(const float* __restrict__ x,
                     const float* __restrict__ alpha,
                     const float* __restrict__ alpha0,
                     const int* __restrict__ y) {
    extern __shared__ float sm[];
    float* salpha = sm;                    // 14*2048
    float* sq     = sm + M_N * F_N;        // 32*14*2  (q0,q1 per row/bit)

    int tid = threadIdx.x;
    for (int idx = tid; idx < M_N * F_N; idx += 256) salpha[idx] = alpha[idx];
    __syncthreads();

    int p  = tid >> 4;
    int cg = tid & 15;
    int r0 = blockIdx.x * 32 + p * 2;
    int r1 = r0 + 1;

    float acc0[M_N], acc1[M_N];
#pragma unroll
    for (int j = 0; j < M_N; j++) { acc0[j] = 0.f; acc1[j] = 0.f; }

    const float* x0 = x + (size_t)r0 * F_N;
    const float* x1 = x + (size_t)r1 * F_N;

#pragma unroll 4
    for (int m = 0; m < 128; m++) {
        int col = cg + (m << 4);
        float xa = x0[col];
        float xb = x1[col];
#pragma unroll
        for (int j = 0; j < M_N; j++) {
            float a = salpha[j * F_N + col];
            acc0[j] = fmaf(xa, a, acc0[j]);
            acc1[j] = fmaf(xb, a, acc1[j]);
        }
    }

#pragma unroll
    for (int j = 0; j < M_N; j++) {
#pragma unroll
        for (int m = 8; m >= 1; m >>= 1) {
            acc0[j] += __shfl_xor_sync(0xffffffffu, acc0[j], m);
            acc1[j] += __shfl_xor_sync(0xffffffffu, acc1[j], m);
        }
    }

    if (cg == 0) {
        float sp_sum = 0.f;
        int lr0 = p * 2, lr1 = p * 2 + 1;
#pragma unroll
        for (int j = 0; j < M_N; j++) {
            float l0 = alpha0[j] + acc0[j];
            float l1 = alpha0[j] + acc1[j];
            g_Le[r0 * M_N + j] = l0;
            g_Le[r1 * M_N + j] = l1;
            // stable sigmoid pair + softplus
            float e0 = expf(-fabsf(l0));
            float e1 = expf(-fabsf(l1));
            float i0 = 1.f / (1.f + e0);
            float i1 = 1.f / (1.f + e1);
            float q1a = (l0 >= 0.f) ? i0 : e0 * i0;   // sigmoid(l0)
            float q0a = (l0 >= 0.f) ? e0 * i0 : i0;   // 1 - sigmoid
            float q1b = (l1 >= 0.f) ? i1 : e1 * i1;
            float q0b = (l1 >= 0.f) ? e1 * i1 : i1;
            sq[(lr0 * M_N + j) * 2 + 0] = q0a;
            sq[(lr0 * M_N + j) * 2 + 1] = q1a;
            sq[(lr1 * M_N + j) * 2 + 0] = q0b;
            sq[(lr1 * M_N + j) * 2 + 1] = q1b;
            sp_sum += fmaxf(l0, 0.f) + log1pf(e0);
            sp_sum += fmaxf(l1, 0.f) + log1pf(e1);
        }
        atomicAdd(&g_acc, -(double)sp_sum);   // -EIV
    }
    __syncthreads();

    // whi'/wlo' via bit-product of q's, scaled by Ehi/Elo of the class
    for (int v = tid; v < 32 * 256; v += 256) {
        int row = v >> 8, rem = v & 255;
        int half = rem >> 7, idx = rem & 127;
        int b = blockIdx.x * 32 + row;
        int c = y[b];
        int base = half ? 7 : 0;
        float prod = half ? __ldg(&g_Elo[c * 128 + idx])
                          : __ldg(&g_Ehi[c * 128 + idx]);
#pragma unroll
        for (int j = 0; j < 7; j++) {
            int bit = (idx >> (6 - j)) & 1;
            prod *= sq[((row * M_N + base + j) << 1) + bit];
        }
        if (half == 0) g_Whi[b * 128 + idx] = prod;
        else           g_Wlo[b * 128 + idx] = prod;
    }
}

// ---------------------------------------------------------------------------
// K_main: 256 blocks x 16 samples (no class grouping needed).
//   V = Dinv * wlo', R = DinvL * wlo', U = Dinv^T * whi'
//   finalize per sample -> double atomic.
// ---------------------------------------------------------------------------
__global__ void __launch_bounds__(512)
k_main(const int* __restrict__ y,
       const float* __restrict__ beta0,
       const float* __restrict__ beta) {
    extern __shared__ float sm[];
    float* sDi   = sm;                       // 128*PAD
    float* sDiL  = sDi + 128 * PAD;          // 128*PAD
    float* sWloT = sDiL + 128 * PAD;         // 128*GRP  (l-major)
    float* sWhiT = sWloT + 128 * GRP;        // 128*GRP  (h-major)
    float* sWloS = sWhiT + 128 * GRP;        // GRP*128  (s-major)
    float* sWhiS = sWloS + GRP * 128;        // GRP*128
    float* sV    = sWhiS + GRP * 128;        // GRP*128
    float* sR    = sV + GRP * 128;           // GRP*128
    float* sU    = sR + GRP * 128;           // GRP*128

    int tid = threadIdx.x;
    int b0s = blockIdx.x * GRP;

    for (int idx = tid; idx < K_N; idx += 512) {
        int h = idx >> 7, l = idx & 127;
        sDi[h * PAD + l]  = g_Dinv[idx];
        sDiL[h * PAD + l] = g_DinvL[idx];
    }
    for (int v = tid; v < GRP * 128; v += 512) {
        int s = v >> 7, idx = v & 127;
        int b = b0s + s;
        float vh = g_Whi[b * 128 + idx];
        float vl = g_Wlo[b * 128 + idx];
        sWhiS[s * 128 + idx] = vh;
        sWloS[s * 128 + idx] = vl;
        sWhiT[idx * GRP + s] = vh;
        sWloT[idx * GRP + s] = vl;
    }
    __syncthreads();

    // fused V/R pass: thread (h, sg) computes V,R for 4 samples
    {
        int h = tid & 127;
        int sg = tid >> 7;      // 0..3
        float accV[4] = {0, 0, 0, 0};
        float accR[4] = {0, 0, 0, 0};
        const float* rowD  = sDi + h * PAD;
        const float* rowDL = sDiL + h * PAD;
#pragma unroll 4
        for (int l = 0; l < 128; l++) {
            float pv = rowD[l];
            float pr = rowDL[l];
            float4 w = *(const float4*)&sWloT[l * GRP + sg * 4];
            accV[0] = fmaf(pv, w.x, accV[0]);
            accV[1] = fmaf(pv, w.y, accV[1]);
            accV[2] = fmaf(pv, w.z, accV[2]);
            accV[3] = fmaf(pv, w.w, accV[3]);
            accR[0] = fmaf(pr, w.x, accR[0]);
            accR[1] = fmaf(pr, w.y, accR[1]);
            accR[2] = fmaf(pr, w.z, accR[2]);
            accR[3] = fmaf(pr, w.w, accR[3]);
        }
#pragma unroll
        for (int q = 0; q < 4; q++) {
            sV[(sg * 4 + q) * 128 + h] = accV[q];
            sR[(sg * 4 + q) * 128 + h] = accR[q];
        }
    }
    // U pass: thread (l, sg): U[s][l] = sum_h Dinv[h][l]*whi'[s][h]
    {
        int l = tid & 127;
        int sg = tid >> 7;
        float acc[4] = {0, 0, 0, 0};
#pragma unroll 4
        for (int h = 0; h < 128; h++) {
            float pv = sDi[h * PAD + l];
            float4 w = *(const float4*)&sWhiT[h * GRP + sg * 4];
            acc[0] = fmaf(pv, w.x, acc[0]);
            acc[1] = fmaf(pv, w.y, acc[1]);
            acc[2] = fmaf(pv, w.z, acc[2]);
            acc[3] = fmaf(pv, w.w, acc[3]);
        }
#pragma unroll
        for (int q = 0; q < 4; q++)
            sU[(sg * 4 + q) * 128 + l] = acc[q];
    }
    __syncthreads();

    // finalize: warp w handles sample w
    int w = tid >> 5, lane = tid & 31;
    {
        float dacc = 0.f, eacc = 0.f;
        float nh[7] = {0, 0, 0, 0, 0, 0, 0};
        float nl[7] = {0, 0, 0, 0, 0, 0, 0};
        float4 whi4 = *(const float4*)&sWhiS[w * 128 + lane * 4];
        float4 wlo4 = *(const float4*)&sWloS[w * 128 + lane * 4];
        float4 V4   = *(const float4*)&sV[w * 128 + lane * 4];
        float4 R4   = *(const float4*)&sR[w * 128 + lane * 4];
        float4 U4   = *(const float4*)&sU[w * 128 + lane * 4];
        const float* whiA = (const float*)&whi4;
        const float* wloA = (const float*)&wlo4;
        const float* VA = (const float*)&V4;
        const float* RA = (const float*)&R4;
        const float* UA = (const float*)&U4;
#pragma unroll
        for (int q = 0; q < 4; q++) {
            int h = lane * 4 + q;
            float wv = whiA[q] * VA[q];
            dacc += wv;
            eacc = fmaf(whiA[q], RA[q], eacc);
            float wu = wloA[q] * UA[q];
#pragma unroll
            for (int j = 0; j < 7; j++) {
                float bit = (float)((h >> (6 - j)) & 1);
                nh[j] = fmaf(bit, wv, nh[j]);
                nl[j] = fmaf(bit, wu, nl[j]);
            }
        }
#pragma unroll
        for (int m = 16; m >= 1; m >>= 1) {
            dacc += __shfl_xor_sync(0xffffffffu, dacc, m);
            eacc += __shfl_xor_sync(0xffffffffu, eacc, m);
#pragma unroll
            for (int j = 0; j < 7; j++) {
                nh[j] += __shfl_xor_sync(0xffffffffu, nh[j], m);
                nl[j] += __shfl_xor_sync(0xffffffffu, nl[j], m);
            }
        }
        if (lane == 0) {
            int b = b0s + w;
            int c = y[b];
            float inv = 1.f / dacc;
            float contrib = beta0[c] - eacc * inv;
#pragma unroll
            for (int j = 0; j < 7; j++) {
                float Ez = nh[j] * inv;
                contrib += (2.f * Ez - 1.f) * beta[c * M_N + j]
                         + Ez * g_Le[b * M_N + j];
            }
#pragma unroll
            for (int j = 7; j < 14; j++) {
                float Ez = nl[j - 7] * inv;
                contrib += (2.f * Ez - 1.f) * beta[c * M_N + j]
                         + Ez * g_Le[b * M_N + j];
            }
            atomicAdd(&g_acc, (double)contrib);
        }
    }
}

__global__ void k_fin(float* out) { out[0] = (float)g_acc; }

extern "C" void kernel_launch(void* const* d_in, const int* in_sizes, int n_in,
                              void* d_out, int out_size) {
    const float* x   = (const float*)d_in[0];
    const int*   y   = (const int*)d_in[1];
    const float* a0  = (const float*)d_in[2];
    const float* al  = (const float*)d_in[3];
    const float* b0  = (const float*)d_in[4];
    const float* be  = (const float*)d_in[5];
    float* out = (float*)d_out;

    const int SMEM1 = (M_N * F_N + 32 * M_N * 2) * 4;
    const int SMEM4 = (2 * 128 * PAD + 2 * 128 * GRP + 5 * GRP * 128) * 4;

    cudaFuncSetAttribute(k_le, cudaFuncAttributeMaxDynamicSharedMemorySize, SMEM1);
    cudaFuncSetAttribute(k_main, cudaFuncAttributeMaxDynamicSharedMemorySize, SMEM4);

    k_init<<<1, 1>>>();
    k_ehilo<<<C_N, 256>>>(b0, be);
    k_D<<<128, 128>>>();
    k_le<<<128, 256, SMEM1>>>(x, al, a0, y);
    k_main<<<B_N / GRP, 512, SMEM4>>>(y, b0, be);
    k_fin<<<1, 1>>>(out);
}

// round 4
// speedup vs baseline: 2.8017x; 1.1746x over previous
#include <cuda_runtime.h>
#include <math.h>

#define B_N 4096
#define F_N 2048
#define M_N 14
#define C_N 100
#define K_N 16384
#define PAD 129
#define GRP 16

__device__ float g_Whi[B_N * 128];
__device__ float g_Wlo[B_N * 128];
__device__ float g_Le[B_N * M_N];
__device__ float g_P[2 * B_N * M_N];    // split-K partials
__device__ float g_Ehi[C_N * 128];
__device__ float g_Elo[C_N * 128];
__device__ float g_Dinv[128 * 128];
__device__ float g_DinvL[128 * 128];
__device__ double g_acc;

__global__ void k_init() { g_acc = 0.0; }

// ---------------------------------------------------------------------------
__global__ void k_ehilo(const float* __restrict__ beta0,
                        const float* __restrict__ beta) {
    int c = blockIdx.x, t = threadIdx.x;
    if (t < 128) {
        int h = t;
        float v = beta0[c];
#pragma unroll
        for (int j = 0; j < 7; j++)
            v += (((h >> (6 - j)) & 1) ? 1.f : -1.f) * beta[c * M_N + j];
        g_Ehi[c * 128 + h] = expf(v);
    } else {
        int l = t - 128;
        float v = 0.f;
#pragma unroll
        for (int j = 0; j < 7; j++)
            v += (((l >> (6 - j)) & 1) ? 1.f : -1.f) * beta[c * M_N + 7 + j];
        g_Elo[c * 128 + l] = expf(v);
    }
}

// ---------------------------------------------------------------------------
__global__ void k_D() {
    int h = blockIdx.x, l = threadIdx.x;
    float d = 0.f;
#pragma unroll 4
    for (int c = 0; c < C_N; c++)
        d = fmaf(__ldg(&g_Ehi[c * 128 + h]), __ldg(&g_Elo[c * 128 + l]), d);
    float inv = 1.f / d;
    g_Dinv[h * 128 + l] = inv;
    g_DinvL[h * 128 + l] = logf(d) * inv;
}

// ---------------------------------------------------------------------------
// GEMM: partial[seg][b][j] = sum over F-half of x[b]*alpha[j].
// grid (256 row-tiles, 2 F-halves), 128 threads. Warp = 4 rows, lanes split
// the 1024-col segment as float4 chunks. 4 rows x 14 accumulators/thread.
// ---------------------------------------------------------------------------
__global__ void __launch_bounds__(128)
k_gemm(const float* __restrict__ x, const float* __restrict__ alpha) {
    int wid = threadIdx.x >> 5, lane = threadIdx.x & 31;
    int r0 = blockIdx.x * 16 + wid * 4;
    int colbase = blockIdx.y * 1024 + lane * 4;

    float acc[4][M_N];
#pragma unroll
    for (int r = 0; r < 4; r++)
#pragma unroll
        for (int j = 0; j < M_N; j++) acc[r][j] = 0.f;

#pragma unroll 2
    for (int k = 0; k < 8; k++) {
        int col = colbase + k * 128;
        float4 xa0 = *(const float4*)&x[(size_t)(r0 + 0) * F_N + col];
        float4 xa1 = *(const float4*)&x[(size_t)(r0 + 1) * F_N + col];
        float4 xa2 = *(const float4*)&x[(size_t)(r0 + 2) * F_N + col];
        float4 xa3 = *(const float4*)&x[(size_t)(r0 + 3) * F_N + col];
#pragma unroll
        for (int j = 0; j < M_N; j++) {
            float4 av = __ldg((const float4*)&alpha[(size_t)j * F_N + col]);
            acc[0][j] = fmaf(xa0.x, av.x, fmaf(xa0.y, av.y,
                        fmaf(xa0.z, av.z, fmaf(xa0.w, av.w, acc[0][j]))));
            acc[1][j] = fmaf(xa1.x, av.x, fmaf(xa1.y, av.y,
                        fmaf(xa1.z, av.z, fmaf(xa1.w, av.w, acc[1][j]))));
            acc[2][j] = fmaf(xa2.x, av.x, fmaf(xa2.y, av.y,
                        fmaf(xa2.z, av.z, fmaf(xa2.w, av.w, acc[2][j]))));
            acc[3][j] = fmaf(xa3.x, av.x, fmaf(xa3.y, av.y,
                        fmaf(xa3.z, av.z, fmaf(xa3.w, av.w, acc[3][j]))));
        }
    }
#pragma unroll
    for (int r = 0; r < 4; r++)
#pragma unroll
        for (int j = 0; j < M_N; j++) {
#pragma unroll
            for (int m = 16; m >= 1; m >>= 1)
                acc[r][j] += __shfl_xor_sync(0xffffffffu, acc[r][j], m);
        }
    if (lane == 0) {
        float* dst = g_P + (size_t)blockIdx.y * B_N * M_N;
#pragma unroll
        for (int r = 0; r < 4; r++)
#pragma unroll
            for (int j = 0; j < M_N; j++)
                dst[(r0 + r) * M_N + j] = acc[r][j];
    }
}

// ---------------------------------------------------------------------------
// Epilogue: le = alpha0 + P0 + P1; EIV; whi'/wlo' via sigmoid products.
// grid 128 x 256 threads; 32 rows/block.
// ---------------------------------------------------------------------------
__global__ void k_post(const float* __restrict__ alpha0,
                       const int* __restrict__ y) {
    __shared__ float sq[32 * M_N * 2];
    __shared__ float ssp[32];
    int tid = threadIdx.x;
    if (tid < 32) {
        int b = blockIdx.x * 32 + tid;
        float sp_sum = 0.f;
#pragma unroll
        for (int j = 0; j < M_N; j++) {
            float le = alpha0[j] + g_P[b * M_N + j] + g_P[B_N * M_N + b * M_N + j];
            g_Le[b * M_N + j] = le;
            float e = expf(-fabsf(le));
            float iv = 1.f / (1.f + e);
            float q1 = (le >= 0.f) ? iv : e * iv;
            float q0 = (le >= 0.f) ? e * iv : iv;
            sq[(tid * M_N + j) * 2 + 0] = q0;
            sq[(tid * M_N + j) * 2 + 1] = q1;
            sp_sum += fmaxf(le, 0.f) + log1pf(e);
        }
        ssp[tid] = sp_sum;
#pragma unroll
        for (int m = 16; m >= 1; m >>= 1)
            sp_sum += __shfl_xor_sync(0xffffffffu, sp_sum, m);
        if (tid == 0) atomicAdd(&g_acc, -(double)sp_sum);   // -EIV
    }
    __syncthreads();

    for (int v = tid; v < 32 * 256; v += 256) {
        int row = v >> 8, rem = v & 255;
        int half = rem >> 7, idx = rem & 127;
        int b = blockIdx.x * 32 + row;
        int c = y[b];
        int base = half ? 7 : 0;
        float prod = half ? __ldg(&g_Elo[c * 128 + idx])
                          : __ldg(&g_Ehi[c * 128 + idx]);
#pragma unroll
        for (int j = 0; j < 7; j++) {
            int bit = (idx >> (6 - j)) & 1;
            prod *= sq[((row * M_N + base + j) << 1) + bit];
        }
        if (half == 0) g_Whi[b * 128 + idx] = prod;
        else           g_Wlo[b * 128 + idx] = prod;
    }
}

// ---------------------------------------------------------------------------
// K_main: 256 blocks x 16 samples. V = Dinv*wlo', R = DinvL*wlo',
// U = Dinv^T*whi'; per-sample finalize; block-reduced double atomic.
// ---------------------------------------------------------------------------
__global__ void __launch_bounds__(512)
k_main(const int* __restrict__ y,
       const float* __restrict__ beta0,
       const float* __restrict__ beta) {
    extern __shared__ float sm[];
    float* sDi   = sm;
    float* sDiL  = sDi + 128 * PAD;
    float* sWloT = sDiL + 128 * PAD;
    float* sWhiT = sWloT + 128 * GRP;
    float* sWloS = sWhiT + 128 * GRP;
    float* sWhiS = sWloS + GRP * 128;
    float* sV    = sWhiS + GRP * 128;
    float* sR    = sV + GRP * 128;
    float* sU    = sR + GRP * 128;
    __shared__ float scontrib[GRP];

    int tid = threadIdx.x;
    int b0s = blockIdx.x * GRP;

    for (int idx = tid; idx < K_N; idx += 512) {
        int h = idx >> 7, l = idx & 127;
        sDi[h * PAD + l]  = g_Dinv[idx];
        sDiL[h * PAD + l] = g_DinvL[idx];
    }
    for (int v = tid; v < GRP * 128; v += 512) {
        int s = v >> 7, idx = v & 127;
        int b = b0s + s;
        float vh = g_Whi[b * 128 + idx];
        float vl = g_Wlo[b * 128 + idx];
        sWhiS[s * 128 + idx] = vh;
        sWloS[s * 128 + idx] = vl;
        sWhiT[idx * GRP + s] = vh;
        sWloT[idx * GRP + s] = vl;
    }
    __syncthreads();

    {
        int h = tid & 127;
        int sg = tid >> 7;
        float accV[4] = {0, 0, 0, 0};
        float accR[4] = {0, 0, 0, 0};
        const float* rowD  = sDi + h * PAD;
        const float* rowDL = sDiL + h * PAD;
#pragma unroll 4
        for (int l = 0; l < 128; l++) {
            float pv = rowD[l];
            float pr = rowDL[l];
            float4 w = *(const float4*)&sWloT[l * GRP + sg * 4];
            accV[0] = fmaf(pv, w.x, accV[0]);
            accV[1] = fmaf(pv, w.y, accV[1]);
            accV[2] = fmaf(pv, w.z, accV[2]);
            accV[3] = fmaf(pv, w.w, accV[3]);
            accR[0] = fmaf(pr, w.x, accR[0]);
            accR[1] = fmaf(pr, w.y, accR[1]);
            accR[2] = fmaf(pr, w.z, accR[2]);
            accR[3] = fmaf(pr, w.w, accR[3]);
        }
#pragma unroll
        for (int q = 0; q < 4; q++) {
            sV[(sg * 4 + q) * 128 + h] = accV[q];
            sR[(sg * 4 + q) * 128 + h] = accR[q];
        }
    }
    {
        int l = tid & 127;
        int sg = tid >> 7;
        float acc[4] = {0, 0, 0, 0};
#pragma unroll 4
        for (int h = 0; h < 128; h++) {
            float pv = sDi[h * PAD + l];
            float4 w = *(const float4*)&sWhiT[h * GRP + sg * 4];
            acc[0] = fmaf(pv, w.x, acc[0]);
            acc[1] = fmaf(pv, w.y, acc[1]);
            acc[2] = fmaf(pv, w.z, acc[2]);
            acc[3] = fmaf(pv, w.w, acc[3]);
        }
#pragma unroll
        for (int q = 0; q < 4; q++)
            sU[(sg * 4 + q) * 128 + l] = acc[q];
    }
    __syncthreads();

    int w = tid >> 5, lane = tid & 31;
    {
        float dacc = 0.f, eacc = 0.f;
        float nh[7] = {0, 0, 0, 0, 0, 0, 0};
        float nl[7] = {0, 0, 0, 0, 0, 0, 0};
        float4 whi4 = *(const float4*)&sWhiS[w * 128 + lane * 4];
        float4 wlo4 = *(const float4*)&sWloS[w * 128 + lane * 4];
        float4 V4   = *(const float4*)&sV[w * 128 + lane * 4];
        float4 R4   = *(const float4*)&sR[w * 128 + lane * 4];
        float4 U4   = *(const float4*)&sU[w * 128 + lane * 4];
        const float* whiA = (const float*)&whi4;
        const float* wloA = (const float*)&wlo4;
        const float* VA = (const float*)&V4;
        const float* RA = (const float*)&R4;
        const float* UA = (const float*)&U4;
#pragma unroll
        for (int q = 0; q < 4; q++) {
            int h = lane * 4 + q;
            float wv = whiA[q] * VA[q];
            dacc += wv;
            eacc = fmaf(whiA[q], RA[q], eacc);
            float wu = wloA[q] * UA[q];
#pragma unroll
            for (int j = 0; j < 7; j++) {
                float bit = (float)((h >> (6 - j)) & 1);
                nh[j] = fmaf(bit, wv, nh[j]);
                nl[j] = fmaf(bit, wu, nl[j]);
            }
        }
#pragma unroll
        for (int m = 16; m >= 1; m >>= 1) {
            dacc += __shfl_xor_sync(0xffffffffu, dacc, m);
            eacc += __shfl_xor_sync(0xffffffffu, eacc, m);
#pragma unroll
            for (int j = 0; j < 7; j++) {
                nh[j] += __shfl_xor_sync(0xffffffffu, nh[j], m);
                nl[j] += __shfl_xor_sync(0xffffffffu, nl[j], m);
            }
        }
        if (lane == 0) {
            int b = b0s + w;
            int c = y[b];
            float inv = 1.f / dacc;
            float contrib = beta0[c] - eacc * inv;
#pragma unroll
            for (int j = 0; j < 7; j++) {
                float Ez = nh[j] * inv;
                contrib += (2.f * Ez - 1.f) * beta[c * M_N + j]
                         + Ez * g_Le[b * M_N + j];
            }
#pragma unroll
            for (int j = 7; j < 14; j++) {
                float Ez = nl[j - 7] * inv;
                contrib += (2.f * Ez - 1.f) * beta[c * M_N + j]
                         + Ez * g_Le[b * M_N + j];
            }
            scontrib[w] = contrib;
        }
    }
    __syncthreads();
    if (tid == 0) {
        float t = 0.f;
#pragma unroll
        for (int s = 0; s < GRP; s++) t += scontrib[s];
        atomicAdd(&g_acc, (double)t);
    }
}

__global__ void k_fin(float* out) { out[0] = (float)g_acc; }

extern "C" void kernel_launch(void* const* d_in, const int* in_sizes, int n_in,
                              void* d_out, int out_size) {
    const float* x   = (const float*)d_in[0];
    const int*   y   = (const int*)d_in[1];
    const float* a0  = (const float*)d_in[2];
    const float* al  = (const float*)d_in[3];
    const float* b0  = (const float*)d_in[4];
    const float* be  = (const float*)d_in[5];
    float* out = (float*)d_out;

    const int SMEM4 = (2 * 128 * PAD + 2 * 128 * GRP + 5 * GRP * 128) * 4;
    cudaFuncSetAttribute(k_main, cudaFuncAttributeMaxDynamicSharedMemorySize, SMEM4);

    k_init<<<1, 1>>>();
    k_ehilo<<<C_N, 256>>>(b0, be);
    k_D<<<128, 128>>>();
    dim3 gg(B_N / 16, 2);
    k_gemm<<<gg, 128>>>(x, al);
    k_post<<<128, 256>>>(a0, y);
    k_main<<<B_N / GRP, 512, SMEM4>>>(y, b0, be);
    k_fin<<<1, 1>>>(out);
}

// round 5
// speedup vs baseline: 3.5347x; 1.2616x over previous
#include <cuda_runtime.h>
#include <math.h>

#define B_N 4096
#define F_N 2048
#define M_N 14
#define C_N 100
#define PAD 129
#define GRP 16
#define SST 132

typedef unsigned long long ull;

__device__ float g_Le[B_N * M_N];
__device__ float g_Ehi[C_N * 128];
__device__ float g_Elo[C_N * 128];
__device__ float g_Dinv[128 * 128];
__device__ float g_DinvL[128 * 128];
__device__ double g_acc;

__device__ __forceinline__ ull fma2(ull a, ull b, ull c) {
    ull d;
    asm("fma.rn.f32x2 %0, %1, %2, %3;" : "=l"(d) : "l"(a), "l"(b), "l"(c));
    return d;
}

// ---------------------------------------------------------------------------
__global__ void k_ehilo(const float* __restrict__ beta0,
                        const float* __restrict__ beta) {
    if (blockIdx.x == 0 && threadIdx.x == 0) g_acc = 0.0;
    int c = blockIdx.x, t = threadIdx.x;
    if (t < 128) {
        int h = t;
        float v = beta0[c];
#pragma unroll
        for (int j = 0; j < 7; j++)
            v += (((h >> (6 - j)) & 1) ? 1.f : -1.f) * beta[c * M_N + j];
        g_Ehi[c * 128 + h] = expf(v);
    } else if (t < 256) {
        int l = t - 128;
        float v = 0.f;
#pragma unroll
        for (int j = 0; j < 7; j++)
            v += (((l >> (6 - j)) & 1) ? 1.f : -1.f) * beta[c * M_N + 7 + j];
        g_Elo[c * 128 + l] = expf(v);
    }
}

// ---------------------------------------------------------------------------
__global__ void k_D() {
    int h = blockIdx.x, l = threadIdx.x;
    float d = 0.f;
#pragma unroll 4
    for (int c = 0; c < C_N; c++)
        d = fmaf(__ldg(&g_Ehi[c * 128 + h]), __ldg(&g_Elo[c * 128 + l]), d);
    float inv = 1.f / d;
    g_Dinv[h * 128 + l] = inv;
    g_DinvL[h * 128 + l] = logf(d) * inv;
}

// ---------------------------------------------------------------------------
// GEMM via packed f32x2 FMA. 128 blocks x 256 thr; warp = 4 rows, lanes split
// columns as float4 (= 2 packed f32x2). alpha through L1 (__ldg), x prefetched.
// ---------------------------------------------------------------------------
__global__ void __launch_bounds__(256, 1)
k_gemm(const float* __restrict__ x, const float* __restrict__ alpha,
       const float* __restrict__ alpha0) {
    int wid = threadIdx.x >> 5, lane = threadIdx.x & 31;
    int r0 = blockIdx.x * 32 + wid * 4;

    ull acc[4][M_N];
#pragma unroll
    for (int r = 0; r < 4; r++)
#pragma unroll
        for (int j = 0; j < M_N; j++) acc[r][j] = 0ull;

    ull xc[4][2], xn[4][2];
#pragma unroll
    for (int r = 0; r < 4; r++) {
        ulonglong2 v = *(const ulonglong2*)&x[(size_t)(r0 + r) * F_N + lane * 4];
        xn[r][0] = v.x; xn[r][1] = v.y;
    }

#pragma unroll 4
    for (int it = 0; it < 16; it++) {
#pragma unroll
        for (int r = 0; r < 4; r++) { xc[r][0] = xn[r][0]; xc[r][1] = xn[r][1]; }
        if (it < 15) {
#pragma unroll
            for (int r = 0; r < 4; r++) {
                ulonglong2 v = *(const ulonglong2*)
                    &x[(size_t)(r0 + r) * F_N + (it + 1) * 128 + lane * 4];
                xn[r][0] = v.x; xn[r][1] = v.y;
            }
        }
        int col = it * 128 + lane * 4;
#pragma unroll
        for (int j = 0; j < M_N; j++) {
            ulonglong2 a2 = __ldg((const ulonglong2*)&alpha[(size_t)j * F_N + col]);
#pragma unroll
            for (int r = 0; r < 4; r++) {
                acc[r][j] = fma2(xc[r][0], a2.x, acc[r][j]);
                acc[r][j] = fma2(xc[r][1], a2.y, acc[r][j]);
            }
        }
    }

#pragma unroll
    for (int r = 0; r < 4; r++)
#pragma unroll
        for (int j = 0; j < M_N; j++) {
            float2 f = *(float2*)&acc[r][j];
            float s = f.x + f.y;
#pragma unroll
            for (int m = 16; m >= 1; m >>= 1)
                s += __shfl_xor_sync(0xffffffffu, s, m);
            if (lane == 0) g_Le[(r0 + r) * M_N + j] = alpha0[j] + s;
        }
}

// ---------------------------------------------------------------------------
// K_main: 256 blocks x 16 samples, 512 threads. Builds whi'/wlo' in-block
// from Le (sigmoid products) + Ehi/Elo; V = Dinv*wlo', R = DinvL*wlo',
// U = Dinv^T*whi'; per-sample finalize incl. EIV; one double atomic/block.
// ---------------------------------------------------------------------------
__global__ void __launch_bounds__(512)
k_main(const int* __restrict__ y,
       const float* __restrict__ beta0,
       const float* __restrict__ beta) {
    extern __shared__ float sm[];
    float* sDi   = sm;                         // 128*PAD
    float* sDiL  = sDi + 128 * PAD;            // 128*PAD
    float* sWhiS = sDiL + 128 * PAD;           // 16*SST
    float* sWloS = sWhiS + GRP * SST;
    float* sV    = sWloS + GRP * SST;
    float* sR    = sV + GRP * SST;
    float* sU    = sR + GRP * SST;
    float* sWhiT = sU + GRP * SST;             // 128*16
    float* sWloT = sWhiT + 128 * GRP;          // 128*16
    float* sq    = sWloT + 128 * GRP;          // 16*14*2
    float* sle   = sq + GRP * M_N * 2;         // 16*14
    __shared__ int   sc[GRP];
    __shared__ float sspw[7];
    __shared__ float scontrib[GRP];

    int tid = threadIdx.x;
    int lane = tid & 31;
    int b0s = blockIdx.x * GRP;

    if (tid < GRP) sc[tid] = y[b0s + tid];

    for (int idx = tid; idx < 128 * 128; idx += 512) {
        int h = idx >> 7, l = idx & 127;
        sDi[h * PAD + l]  = g_Dinv[idx];
        sDiL[h * PAD + l] = g_DinvL[idx];
    }

    if (tid < 224) {
        int s = tid / M_N, j = tid % M_N;
        float le = g_Le[(b0s + s) * M_N + j];
        sle[s * M_N + j] = le;
        float e = expf(-fabsf(le));
        float iv = 1.f / (1.f + e);
        sq[(s * M_N + j) * 2 + 0] = (le >= 0.f) ? e * iv : iv;   // P(bit=0)
        sq[(s * M_N + j) * 2 + 1] = (le >= 0.f) ? iv : e * iv;   // P(bit=1)
        float sp = fmaxf(le, 0.f) + log1pf(e);
#pragma unroll
        for (int m = 16; m >= 1; m >>= 1)
            sp += __shfl_xor_sync(0xffffffffu, sp, m);
        if (lane == 0) sspw[tid >> 5] = sp;
    }
    __syncthreads();

    // whi'/wlo' (S layout)
    for (int v = tid; v < GRP * 128; v += 512) {
        int s = v >> 7, idx = v & 127;
        int c = sc[s];
        float ph = __ldg(&g_Ehi[c * 128 + idx]);
        float pl = __ldg(&g_Elo[c * 128 + idx]);
#pragma unroll
        for (int j = 0; j < 7; j++) {
            int bit = (idx >> (6 - j)) & 1;
            ph *= sq[(s * M_N + j) * 2 + bit];
            pl *= sq[(s * M_N + 7 + j) * 2 + bit];
        }
        sWhiS[s * SST + idx] = ph;
        sWloS[s * SST + idx] = pl;
    }
    __syncthreads();
    // transpose to T layout (coalesced writes)
    for (int v = tid; v < GRP * 128; v += 512) {
        int idx = v >> 4, s = v & 15;
        sWhiT[idx * GRP + s] = sWhiS[s * SST + idx];
        sWloT[idx * GRP + s] = sWloS[s * SST + idx];
    }
    __syncthreads();

    // fused V/R pass
    {
        int h = tid & 127;
        int sg = tid >> 7;
        float accV[4] = {0, 0, 0, 0};
        float accR[4] = {0, 0, 0, 0};
        const float* rowD  = sDi + h * PAD;
        const float* rowDL = sDiL + h * PAD;
#pragma unroll 4
        for (int l = 0; l < 128; l++) {
            float pv = rowD[l];
            float pr = rowDL[l];
            float4 w = *(const float4*)&sWloT[l * GRP + sg * 4];
            accV[0] = fmaf(pv, w.x, accV[0]);
            accV[1] = fmaf(pv, w.y, accV[1]);
            accV[2] = fmaf(pv, w.z, accV[2]);
            accV[3] = fmaf(pv, w.w, accV[3]);
            accR[0] = fmaf(pr, w.x, accR[0]);
            accR[1] = fmaf(pr, w.y, accR[1]);
            accR[2] = fmaf(pr, w.z, accR[2]);
            accR[3] = fmaf(pr, w.w, accR[3]);
        }
#pragma unroll
        for (int q = 0; q < 4; q++) {
            sV[(sg * 4 + q) * SST + h] = accV[q];
            sR[(sg * 4 + q) * SST + h] = accR[q];
        }
    }
    // U pass
    {
        int l = tid & 127;
        int sg = tid >> 7;
        float acc[4] = {0, 0, 0, 0};
#pragma unroll 4
        for (int h = 0; h < 128; h++) {
            float pv = sDi[h * PAD + l];
            float4 w = *(const float4*)&sWhiT[h * GRP + sg * 4];
            acc[0] = fmaf(pv, w.x, acc[0]);
            acc[1] = fmaf(pv, w.y, acc[1]);
            acc[2] = fmaf(pv, w.z, acc[2]);
            acc[3] = fmaf(pv, w.w, acc[3]);
        }
#pragma unroll
        for (int q = 0; q < 4; q++)
            sU[(sg * 4 + q) * SST + l] = acc[q];
    }
    __syncthreads();

    // finalize: warp w -> sample w
    int w = tid >> 5;
    {
        float dacc = 0.f, eacc = 0.f;
        float nh[7] = {0, 0, 0, 0, 0, 0, 0};
        float nl[7] = {0, 0, 0, 0, 0, 0, 0};
        float4 whi4 = *(const float4*)&sWhiS[w * SST + lane * 4];
        float4 wlo4 = *(const float4*)&sWloS[w * SST + lane * 4];
        float4 V4   = *(const float4*)&sV[w * SST + lane * 4];
        float4 R4   = *(const float4*)&sR[w * SST + lane * 4];
        float4 U4   = *(const float4*)&sU[w * SST + lane * 4];
        const float* whiA = (const float*)&whi4;
        const float* wloA = (const float*)&wlo4;
        const float* VA = (const float*)&V4;
        const float* RA = (const float*)&R4;
        const float* UA = (const float*)&U4;
#pragma unroll
        for (int q = 0; q < 4; q++) {
            int h = lane * 4 + q;
            float wv = whiA[q] * VA[q];
            dacc += wv;
            eacc = fmaf(whiA[q], RA[q], eacc);
            float wu = wloA[q] * UA[q];
#pragma unroll
            for (int j = 0; j < 7; j++) {
                float bit = (float)((h >> (6 - j)) & 1);
                nh[j] = fmaf(bit, wv, nh[j]);
                nl[j] = fmaf(bit, wu, nl[j]);
            }
        }
#pragma unroll
        for (int m = 16; m >= 1; m >>= 1) {
            dacc += __shfl_xor_sync(0xffffffffu, dacc, m);
            eacc += __shfl_xor_sync(0xffffffffu, eacc, m);
#pragma unroll
            for (int j = 0; j < 7; j++) {
                nh[j] += __shfl_xor_sync(0xffffffffu, nh[j], m);
                nl[j] += __shfl_xor_sync(0xffffffffu, nl[j], m);
            }
        }
        if (lane == 0) {
            int c = sc[w];
            float inv = 1.f / dacc;
            float contrib = beta0[c] - eacc * inv;
#pragma unroll
            for (int j = 0; j < 7; j++) {
                float Ez = nh[j] * inv;
                contrib += (2.f * Ez - 1.f) * beta[c * M_N + j]
                         + Ez * sle[w * M_N + j];
            }
#pragma unroll
            for (int j = 7; j < 14; j++) {
                float Ez = nl[j - 7] * inv;
                contrib += (2.f * Ez - 1.f) * beta[c * M_N + j]
                         + Ez * sle[w * M_N + j];
            }
            scontrib[w] = contrib;
        }
    }
    __syncthreads();
    if (tid == 0) {
        float t = 0.f;
#pragma unroll
        for (int s = 0; s < GRP; s++) t += scontrib[s];
#pragma unroll
        for (int q = 0; q < 7; q++) t -= sspw[q];   // -EIV
        atomicAdd(&g_acc, (double)t);
    }
}

__global__ void k_fin(float* out) { out[0] = (float)g_acc; }

extern "C" void kernel_launch(void* const* d_in, const int* in_sizes, int n_in,
                              void* d_out, int out_size) {
    const float* x   = (const float*)d_in[0];
    const int*   y   = (const int*)d_in[1];
    const float* a0  = (const float*)d_in[2];
    const float* al  = (const float*)d_in[3];
    const float* b0  = (const float*)d_in[4];
    const float* be  = (const float*)d_in[5];
    float* out = (float*)d_out;

    const int SMEM4 = (2 * 128 * PAD + 5 * GRP * SST + 2 * 128 * GRP
                       + GRP * M_N * 2 + GRP * M_N) * 4;
    cudaFuncSetAttribute(k_main, cudaFuncAttributeMaxDynamicSharedMemorySize, SMEM4);

    k_ehilo<<<C_N, 256>>>(b0, be);
    k_D<<<128, 128>>>();
    k_gemm<<<B_N / 32, 256>>>(x, al, a0);
    k_main<<<B_N / GRP, 512, SMEM4>>>(y, b0, be);
    k_fin<<<1, 1>>>(out);
}

// round 8
// speedup vs baseline: 3.7003x; 1.0468x over previous
#include <cuda_runtime.h>
#include <math.h>

#define B_N 4096
#define F_N 2048
#define M_N 14
#define C_N 100
#define GRP 16
#define SST 132

typedef unsigned long long ull;

__device__ float g_Le[B_N * M_N];
__device__ float g_Ehi[C_N * 128];
__device__ float g_Elo[C_N * 128];
__device__ float g_Dinv[128 * 128];
__device__ float g_DinvL[128 * 128];
__device__ double g_acc;

__device__ __forceinline__ ull fma2(ull a, ull b, ull c) {
    ull d;
    asm("fma.rn.f32x2 %0, %1, %2, %3;" : "=l"(d) : "l"(a), "l"(b), "l"(c));
    return d;
}
__device__ __forceinline__ ull pk2(float v) {
    ull r;
    asm("mov.b64 %0, {%1, %1};" : "=l"(r) : "f"(v));
    return r;
}
__device__ __forceinline__ float hsum2(ull a) {
    float2 f = *(float2*)&a;
    return f.x + f.y;
}

// ---------------------------------------------------------------------------
__global__ void k_ehilo(const float* __restrict__ beta0,
                        const float* __restrict__ beta) {
    if (blockIdx.x == 0 && threadIdx.x == 0) g_acc = 0.0;
    int c = blockIdx.x, t = threadIdx.x;
    if (t < 128) {
        int h = t;
        float v = beta0[c];
#pragma unroll
        for (int j = 0; j < 7; j++)
            v += (((h >> (6 - j)) & 1) ? 1.f : -1.f) * beta[c * M_N + j];
        g_Ehi[c * 128 + h] = expf(v);
    } else if (t < 256) {
        int l = t - 128;
        float v = 0.f;
#pragma unroll
        for (int j = 0; j < 7; j++)
            v += (((l >> (6 - j)) & 1) ? 1.f : -1.f) * beta[c * M_N + 7 + j];
        g_Elo[c * 128 + l] = expf(v);
    }
}

// ---------------------------------------------------------------------------
__global__ void k_D() {
    int h = blockIdx.x, l = threadIdx.x;
    float d = 0.f;
#pragma unroll 4
    for (int c = 0; c < C_N; c++)
        d = fmaf(__ldg(&g_Ehi[c * 128 + h]), __ldg(&g_Elo[c * 128 + l]), d);
    float inv = 1.f / d;
    g_Dinv[h * 128 + l] = inv;
    g_DinvL[h * 128 + l] = logf(d) * inv;
}

// ---------------------------------------------------------------------------
// GEMM via packed f32x2 FMA. 256 blocks x 128 thr (4 warps x 4 rows).
// ---------------------------------------------------------------------------
__global__ void __launch_bounds__(128)
k_gemm(const float* __restrict__ x, const float* __restrict__ alpha,
       const float* __restrict__ alpha0) {
    int wid = threadIdx.x >> 5, lane = threadIdx.x & 31;
    int r0 = blockIdx.x * 16 + wid * 4;

    ull acc[4][M_N];
#pragma unroll
    for (int r = 0; r < 4; r++)
#pragma unroll
        for (int j = 0; j < M_N; j++) acc[r][j] = 0ull;

    ull xc[4][2], xn[4][2];
#pragma unroll
    for (int r = 0; r < 4; r++) {
        ulonglong2 v = *(const ulonglong2*)&x[(size_t)(r0 + r) * F_N + lane * 4];
        xn[r][0] = v.x; xn[r][1] = v.y;
    }

#pragma unroll 4
    for (int it = 0; it < 16; it++) {
#pragma unroll
        for (int r = 0; r < 4; r++) { xc[r][0] = xn[r][0]; xc[r][1] = xn[r][1]; }
        if (it < 15) {
#pragma unroll
            for (int r = 0; r < 4; r++) {
                ulonglong2 v = *(const ulonglong2*)
                    &x[(size_t)(r0 + r) * F_N + (it + 1) * 128 + lane * 4];
                xn[r][0] = v.x; xn[r][1] = v.y;
            }
        }
        int col = it * 128 + lane * 4;
#pragma unroll
        for (int j = 0; j < M_N; j++) {
            ulonglong2 a2 = __ldg((const ulonglong2*)&alpha[(size_t)j * F_N + col]);
#pragma unroll
            for (int r = 0; r < 4; r++) {
                acc[r][j] = fma2(xc[r][0], a2.x, acc[r][j]);
                acc[r][j] = fma2(xc[r][1], a2.y, acc[r][j]);
            }
        }
    }

#pragma unroll
    for (int r = 0; r < 4; r++)
#pragma unroll
        for (int j = 0; j < M_N; j++) {
            float s = hsum2(acc[r][j]);
#pragma unroll
            for (int m = 16; m >= 1; m >>= 1)
                s += __shfl_xor_sync(0xffffffffu, s, m);
            if (lane == 0) g_Le[(r0 + r) * M_N + j] = alpha0[j] + s;
        }
}

// ---------------------------------------------------------------------------
// K_main: 128 blocks x 2 chunks x 16 samples, 512 threads.
// Dinv/DinvL in swizzled smem (phys = h*128 + (l ^ ((h&7)<<2))).
// V = Dinv*wlo', R = DinvL*wlo', U = Dinv^T*whi' via f32x2 FMA.
// ---------------------------------------------------------------------------
__global__ void __launch_bounds__(512)
k_main(const int* __restrict__ y,
       const float* __restrict__ beta0,
       const float* __restrict__ beta) {
    extern __shared__ float sm[];
    float* sDi   = sm;                         // 128*128 swizzled
    float* sDiL  = sDi + 128 * 128;
    float* sWhiS = sDiL + 128 * 128;           // 16*SST
    float* sWloS = sWhiS + GRP * SST;
    float* sV    = sWloS + GRP * SST;
    float* sR    = sV + GRP * SST;
    float* sU    = sR + GRP * SST;
    float* sWhiT = sU + GRP * SST;             // 128*16
    float* sq    = sWhiT + 128 * GRP;          // 16*14*2
    float* sle   = sq + GRP * M_N * 2;         // 16*14
    __shared__ int   sc[GRP];
    __shared__ float sspw[7];
    __shared__ float scontrib[GRP];

    int tid = threadIdx.x;
    int lane = tid & 31;

    // stage Dinv/DinvL with quad swizzle (once per block)
    for (int qg = tid; qg < 4096; qg += 512) {
        int h = qg >> 5, q = qg & 31;
        int pq = q ^ (h & 7);
        ((float4*)sDi)[h * 32 + pq]  = ((const float4*)g_Dinv)[qg];
        ((float4*)sDiL)[h * 32 + pq] = ((const float4*)g_DinvL)[qg];
    }

    float block_acc = 0.f;

    for (int chunk = 0; chunk < 2; chunk++) {
        int b0s = blockIdx.x * 32 + chunk * GRP;

        if (tid < GRP) sc[tid] = y[b0s + tid];
        if (tid < 224) {
            int s = tid / M_N, j = tid % M_N;
            float le = g_Le[(b0s + s) * M_N + j];
            sle[s * M_N + j] = le;
            float e = expf(-fabsf(le));
            float iv = 1.f / (1.f + e);
            sq[(s * M_N + j) * 2 + 0] = (le >= 0.f) ? e * iv : iv;
            sq[(s * M_N + j) * 2 + 1] = (le >= 0.f) ? iv : e * iv;
            float sp = fmaxf(le, 0.f) + log1pf(e);
#pragma unroll
            for (int m = 16; m >= 1; m >>= 1)
                sp += __shfl_xor_sync(0xffffffffu, sp, m);
            if (lane == 0) sspw[tid >> 5] = sp;
        }
        __syncthreads();

        // whi'/wlo' (S layout)
        for (int v = tid; v < GRP * 128; v += 512) {
            int s = v >> 7, idx = v & 127;
            int c = sc[s];
            float ph = __ldg(&g_Ehi[c * 128 + idx]);
            float pl = __ldg(&g_Elo[c * 128 + idx]);
#pragma unroll
            for (int j = 0; j < 7; j++) {
                int bit = (idx >> (6 - j)) & 1;
                ph *= sq[(s * M_N + j) * 2 + bit];
                pl *= sq[(s * M_N + 7 + j) * 2 + bit];
            }
            sWhiS[s * SST + idx] = ph;
            sWloS[s * SST + idx] = pl;
        }
        __syncthreads();
        // whiT (for U pass)
        for (int v = tid; v < GRP * 128; v += 512) {
            int idx = v >> 4, s = v & 15;
            sWhiT[idx * GRP + s] = sWhiS[s * SST + idx];
        }
        __syncthreads();

        // ---- V/R pass: thread (h, sg), f32x2 over l-pairs ----
        {
            int h = tid & 127;
            int sg = tid >> 7;
            int hm = h & 7;
            const float* rowD = sDi + h * 128;
            const float* wb = sWloS + sg * 4 * SST;
            ull aV[4][2], aR[4][2];
#pragma unroll
            for (int s = 0; s < 4; s++) {
                aV[s][0] = aV[s][1] = 0ull;
                aR[s][0] = aR[s][1] = 0ull;
            }
#pragma unroll
            for (int q0 = 0; q0 < 32; q0 += 8) {
#pragma unroll
                for (int c = 0; c < 8; c++) {
                    int pq = q0 + (c ^ hm);     // physical quad (swizzled)
                    int ql = q0 + c;            // logical quad
                    ulonglong2 d2 = *(const ulonglong2*)(rowD + pq * 4);
                    ulonglong2 e2 = *(const ulonglong2*)(rowD + 16384 + pq * 4);
#pragma unroll
                    for (int s = 0; s < 4; s++) {
                        ulonglong2 w2 = *(const ulonglong2*)(wb + s * SST + ql * 4);
                        aV[s][0] = fma2(d2.x, w2.x, aV[s][0]);
                        aV[s][1] = fma2(d2.y, w2.y, aV[s][1]);
                        aR[s][0] = fma2(e2.x, w2.x, aR[s][0]);
                        aR[s][1] = fma2(e2.y, w2.y, aR[s][1]);
                    }
                }
            }
#pragma unroll
            for (int s = 0; s < 4; s++) {
                sV[(sg * 4 + s) * SST + h] = hsum2(aV[s][0]) + hsum2(aV[s][1]);
                sR[(sg * 4 + s) * SST + h] = hsum2(aR[s][0]) + hsum2(aR[s][1]);
            }
        }
        // ---- U pass: thread (l, sg), f32x2 over sample pairs ----
        {
            int l = tid & 127;
            int sg = tid >> 7;
            ull aU0 = 0ull, aU1 = 0ull;
#pragma unroll 2
            for (int h0 = 0; h0 < 128; h0 += 8) {
#pragma unroll
                for (int c = 0; c < 8; c++) {
                    int hh = h0 + c;
                    float pv = sDi[hh * 128 + (l ^ (c << 2))];
                    ull ppv = pk2(pv);
                    ulonglong2 w2 = *(const ulonglong2*)(sWhiT + hh * GRP + sg * 4);
                    aU0 = fma2(ppv, w2.x, aU0);
                    aU1 = fma2(ppv, w2.y, aU1);
                }
            }
            float2 u01 = *(float2*)&aU0;
            float2 u23 = *(float2*)&aU1;
            sU[(sg * 4 + 0) * SST + l] = u01.x;
            sU[(sg * 4 + 1) * SST + l] = u01.y;
            sU[(sg * 4 + 2) * SST + l] = u23.x;
            sU[(sg * 4 + 3) * SST + l] = u23.y;
        }
        __syncthreads();

        // ---- finalize: warp w -> sample w ----
        int w = tid >> 5;
        {
            float dacc = 0.f, eacc = 0.f;
            float nh[7] = {0, 0, 0, 0, 0, 0, 0};
            float nl[7] = {0, 0, 0, 0, 0, 0, 0};
            float4 whi4 = *(const float4*)&sWhiS[w * SST + lane * 4];
            float4 wlo4 = *(const float4*)&sWloS[w * SST + lane * 4];
            float4 V4   = *(const float4*)&sV[w * SST + lane * 4];
            float4 R4   = *(const float4*)&sR[w * SST + lane * 4];
            float4 U4   = *(const float4*)&sU[w * SST + lane * 4];
            const float* whiA = (const float*)&whi4;
            const float* wloA = (const float*)&wlo4;
            const float* VA = (const float*)&V4;
            const float* RA = (const float*)&R4;
            const float* UA = (const float*)&U4;
#pragma unroll
            for (int q = 0; q < 4; q++) {
                int h = lane * 4 + q;
                float wv = whiA[q] * VA[q];
                dacc += wv;
                eacc = fmaf(whiA[q], RA[q], eacc);
                float wu = wloA[q] * UA[q];
#pragma unroll
                for (int j = 0; j < 7; j++) {
                    float bit = (float)((h >> (6 - j)) & 1);
                    nh[j] = fmaf(bit, wv, nh[j]);
                    nl[j] = fmaf(bit, wu, nl[j]);
                }
            }
#pragma unroll
            for (int m = 16; m >= 1; m >>= 1) {
                dacc += __shfl_xor_sync(0xffffffffu, dacc, m);
                eacc += __shfl_xor_sync(0xffffffffu, eacc, m);
#pragma unroll
                for (int j = 0; j < 7; j++) {
                    nh[j] += __shfl_xor_sync(0xffffffffu, nh[j], m);
                    nl[j] += __shfl_xor_sync(0xffffffffu, nl[j], m);
                }
            }
            if (lane == 0) {
                int c = sc[w];
                float inv = 1.f / dacc;
                float contrib = beta0[c] - eacc * inv;
#pragma unroll
                for (int j = 0; j < 7; j++) {
                    float Ez = nh[j] * inv;
                    contrib += (2.f * Ez - 1.f) * beta[c * M_N + j]
                             + Ez * sle[w * M_N + j];
                }
#pragma unroll
                for (int j = 7; j < 14; j++) {
                    float Ez = nl[j - 7] * inv;
                    contrib += (2.f * Ez - 1.f) * beta[c * M_N + j]
                             + Ez * sle[w * M_N + j];
                }
                scontrib[w] = contrib;
            }
        }
        __syncthreads();
        if (tid == 0) {
            float t = 0.f;
#pragma unroll
            for (int s = 0; s < GRP; s++) t += scontrib[s];
#pragma unroll
            for (int q = 0; q < 7; q++) t -= sspw[q];   // -EIV
            block_acc += t;
        }
        __syncthreads();
    }

    if (tid == 0) atomicAdd(&g_acc, (double)block_acc);
}

__global__ void k_fin(float* out) { out[0] = (float)g_acc; }

extern "C" void kernel_launch(void* const* d_in, const int* in_sizes, int n_in,
                              void* d_out, int out_size) {
    const float* x   = (const float*)d_in[0];
    const int*   y   = (const int*)d_in[1];
    const float* a0  = (const float*)d_in[2];
    const float* al  = (const float*)d_in[3];
    const float* b0  = (const float*)d_in[4];
    const float* be  = (const float*)d_in[5];
    float* out = (float*)d_out;

    const int SMEM4 = (2 * 128 * 128 + 5 * GRP * SST + 128 * GRP
                       + GRP * M_N * 2 + GRP * M_N) * 4;
    cudaFuncSetAttribute(k_main, cudaFuncAttributeMaxDynamicSharedMemorySize, SMEM4);

    k_ehilo<<<C_N, 256>>>(b0, be);
    k_D<<<128, 128>>>();
    k_gemm<<<B_N / 16, 128>>>(x, al, a0);
    k_main<<<B_N / 32, 512, SMEM4>>>(y, b0, be);
    k_fin<<<1, 1>>>(out);
}

// round 10
// speedup vs baseline: 3.9697x; 1.0728x over previous
#include <cuda_runtime.h>
#include <math.h>

#define B_N 4096
#define F_N 2048
#define M_N 14
#define C_N 100
#define SMP 32          // samples per k_main block

typedef unsigned long long ull;

__device__ float g_Le[B_N * M_N];
__device__ float g_Ehi[C_N * 128];
__device__ float g_Elo[C_N * 128];
__device__ float g_Dinv[128 * 128];
__device__ float g_DinvL[128 * 128];
__device__ double g_acc;

__device__ __forceinline__ ull fma2(ull a, ull b, ull c) {
    ull d;
    asm("fma.rn.f32x2 %0, %1, %2, %3;" : "=l"(d) : "l"(a), "l"(b), "l"(c));
    return d;
}
__device__ __forceinline__ ull pk2(float v) {
    ull r;
    asm("mov.b64 %0, {%1, %1};" : "=l"(r) : "f"(v));
    return r;
}
__device__ __forceinline__ ull pkab(float a, float b) {
    ull r;
    asm("mov.b64 %0, {%1, %2};" : "=l"(r) : "f"(a), "f"(b));
    return r;
}
__device__ __forceinline__ float hsum2(ull a) {
    float2 f = *(float2*)&a;
    return f.x + f.y;
}

// ---------------------------------------------------------------------------
__global__ void k_ehilo(const float* __restrict__ beta0,
                        const float* __restrict__ beta) {
    if (blockIdx.x == 0 && threadIdx.x == 0) g_acc = 0.0;
    int c = blockIdx.x, t = threadIdx.x;
    if (t < 128) {
        int h = t;
        float v = beta0[c];
#pragma unroll
        for (int j = 0; j < 7; j++)
            v += (((h >> (6 - j)) & 1) ? 1.f : -1.f) * beta[c * M_N + j];
        g_Ehi[c * 128 + h] = expf(v);
    } else if (t < 256) {
        int l = t - 128;
        float v = 0.f;
#pragma unroll
        for (int j = 0; j < 7; j++)
            v += (((l >> (6 - j)) & 1) ? 1.f : -1.f) * beta[c * M_N + 7 + j];
        g_Elo[c * 128 + l] = expf(v);
    }
}

// ---------------------------------------------------------------------------
__global__ void k_D() {
    int h = blockIdx.x, l = threadIdx.x;
    float d = 0.f;
#pragma unroll 4
    for (int c = 0; c < C_N; c++)
        d = fmaf(__ldg(&g_Ehi[c * 128 + h]), __ldg(&g_Elo[c * 128 + l]), d);
    float inv = 1.f / d;
    g_Dinv[h * 128 + l] = inv;
    g_DinvL[h * 128 + l] = logf(d) * inv;
}

// ---------------------------------------------------------------------------
// GEMM: row-pair packed f32x2. 128 blocks x 128 thr; warp = 8 rows
// (4 row-pairs), lane = 4 columns per 128-col iter. alpha broadcast via pk2.
// ---------------------------------------------------------------------------
__global__ void __launch_bounds__(128)
k_gemm(const float* __restrict__ x, const float* __restrict__ alpha,
       const float* __restrict__ alpha0) {
    int wid = threadIdx.x >> 5, lane = threadIdx.x & 31;
    int r0 = blockIdx.x * 32 + wid * 8;

    ull acc[4][M_N];
#pragma unroll
    for (int p = 0; p < 4; p++)
#pragma unroll
        for (int j = 0; j < M_N; j++) acc[p][j] = 0ull;

    float4 xn[8];
#pragma unroll
    for (int r = 0; r < 8; r++)
        xn[r] = *(const float4*)&x[(size_t)(r0 + r) * F_N + lane * 4];

    for (int it = 0; it < 16; it++) {
        int col = it * 128 + lane * 4;
        ull xp[4][4];
#pragma unroll
        for (int p = 0; p < 4; p++) {
            xp[p][0] = pkab(xn[2 * p].x, xn[2 * p + 1].x);
            xp[p][1] = pkab(xn[2 * p].y, xn[2 * p + 1].y);
            xp[p][2] = pkab(xn[2 * p].z, xn[2 * p + 1].z);
            xp[p][3] = pkab(xn[2 * p].w, xn[2 * p + 1].w);
        }
        if (it < 15) {
#pragma unroll
            for (int r = 0; r < 8; r++)
                xn[r] = *(const float4*)&x[(size_t)(r0 + r) * F_N + col + 128];
        }
#pragma unroll
        for (int j = 0; j < M_N; j++) {
            float4 av = __ldg((const float4*)&alpha[(size_t)j * F_N + col]);
            ull a0 = pk2(av.x), a1 = pk2(av.y), a2 = pk2(av.z), a3 = pk2(av.w);
#pragma unroll
            for (int p = 0; p < 4; p++) {
                acc[p][j] = fma2(xp[p][0], a0, acc[p][j]);
                acc[p][j] = fma2(xp[p][1], a1, acc[p][j]);
                acc[p][j] = fma2(xp[p][2], a2, acc[p][j]);
                acc[p][j] = fma2(xp[p][3], a3, acc[p][j]);
            }
        }
    }

#pragma unroll
    for (int p = 0; p < 4; p++)
#pragma unroll
        for (int j = 0; j < M_N; j++) {
            float2 f = *(float2*)&acc[p][j];
#pragma unroll
            for (int m = 16; m >= 1; m >>= 1) {
                f.x += __shfl_xor_sync(0xffffffffu, f.x, m);
                f.y += __shfl_xor_sync(0xffffffffu, f.y, m);
            }
            if (lane == 0) {
                float a0v = alpha0[j];
                g_Le[(r0 + 2 * p) * M_N + j]     = a0v + f.x;
                g_Le[(r0 + 2 * p + 1) * M_N + j] = a0v + f.y;
            }
        }
}

// ---------------------------------------------------------------------------
// K_main: 128 blocks x 1024 thr, 32 samples/block.
// V = Dinv*wlo', U = Dinv^T*whi'; eii folded into V/R pass.
// ---------------------------------------------------------------------------
__global__ void __launch_bounds__(1024)
k_main(const int* __restrict__ y,
       const float* __restrict__ beta0,
       const float* __restrict__ beta) {
    extern __shared__ float sm[];
    float* sDi   = sm;                    // 128*128 swizzled
    float* sDiL  = sDi + 16384;           // 128*128 swizzled
    float* sWhiS = sDiL + 16384;          // 32*128
    float* sWloS = sWhiS + 4096;          // 32*128
    float* sV    = sWloS + 4096;          // 32*128
    float* sU    = sV + 4096;             // 32*128
    float* sWhiT = sU + 4096;             // 128*36 (pad stride 36)
    float* sq    = sWhiT + 4608;          // 32*14*2
    float* sle   = sq + 896;              // 32*14
    __shared__ int   sc[SMP];
    __shared__ float sEiiP[SMP * 4];
    __shared__ float sspw[14];
    __shared__ float scontrib[SMP];

    int tid = threadIdx.x, lane = tid & 31;
    int b0s = blockIdx.x * SMP;

    if (tid < SMP) sc[tid] = y[b0s + tid];

    // Dinv/DinvL staging with quad swizzle
    for (int qg = tid; qg < 4096; qg += 1024) {
        int h = qg >> 5, q = qg & 31;
        int pq = q ^ (h & 7);
        ((float4*)sDi)[h * 32 + pq]  = ((const float4*)g_Dinv)[qg];
        ((float4*)sDiL)[h * 32 + pq] = ((const float4*)g_DinvL)[qg];
    }

    // sq (sigmoid pair) + softplus partials
    if (tid < SMP * M_N) {          // 448 threads = warps 0..13 fully
        int s = tid / M_N, j = tid % M_N;
        float le = g_Le[(b0s + s) * M_N + j];
        sle[s * M_N + j] = le;
        float e = expf(-fabsf(le));
        float iv = 1.f / (1.f + e);
        sq[(s * M_N + j) * 2 + 0] = (le >= 0.f) ? e * iv : iv;
        sq[(s * M_N + j) * 2 + 1] = (le >= 0.f) ? iv : e * iv;
        float sp = fmaxf(le, 0.f) + log1pf(e);
#pragma unroll
        for (int m = 16; m >= 1; m >>= 1)
            sp += __shfl_xor_sync(0xffffffffu, sp, m);
        if (lane == 0) sspw[tid >> 5] = sp;
    }
    __syncthreads();

    // whi'/wlo' staging (S layout + T layout for whi)
    for (int v = tid; v < SMP * 128; v += 1024) {
        int s = v >> 7, idx = v & 127;
        int c = sc[s];
        float ph = __ldg(&g_Ehi[c * 128 + idx]);
        float pl = __ldg(&g_Elo[c * 128 + idx]);
#pragma unroll
        for (int j = 0; j < 7; j++) {
            int bit = (idx >> (6 - j)) & 1;
            ph *= sq[(s * M_N + j) * 2 + bit];
            pl *= sq[(s * M_N + 7 + j) * 2 + bit];
        }
        sWhiS[s * 128 + idx] = ph;
        sWloS[s * 128 + idx] = pl;
        sWhiT[idx * 36 + s] = ph;
    }
    __syncthreads();

    // ---- V pass + eii partials: thread (h, sg), 4 samples ----
    {
        int h = tid & 127, sg = tid >> 7;    // sg 0..7
        int sb = sg * 4;
        int hm = h & 7;
        const float* rowD = sDi + h * 128;
        const float* wb = sWloS + sb * 128;
        ull aV[4], aR[4];
#pragma unroll
        for (int s = 0; s < 4; s++) { aV[s] = 0ull; aR[s] = 0ull; }
#pragma unroll
        for (int q0 = 0; q0 < 32; q0 += 8) {
#pragma unroll
            for (int c = 0; c < 8; c++) {
                int pq = q0 + (c ^ hm);
                int ql = q0 + c;
                ulonglong2 d2 = *(const ulonglong2*)(rowD + pq * 4);
                ulonglong2 e2 = *(const ulonglong2*)(rowD + 16384 + pq * 4);
#pragma unroll
                for (int s = 0; s < 4; s++) {
                    ulonglong2 w2 = *(const ulonglong2*)(wb + s * 128 + ql * 4);
                    aV[s] = fma2(d2.y, w2.y, fma2(d2.x, w2.x, aV[s]));
                    aR[s] = fma2(e2.y, w2.y, fma2(e2.x, w2.x, aR[s]));
                }
            }
        }
#pragma unroll
        for (int s = 0; s < 4; s++) {
            sV[(sb + s) * 128 + h] = hsum2(aV[s]);
            float ep = sWhiS[(sb + s) * 128 + h] * hsum2(aR[s]);
#pragma unroll
            for (int m = 16; m >= 1; m >>= 1)
                ep += __shfl_xor_sync(0xffffffffu, ep, m);
            if (lane == 0) sEiiP[(sb + s) * 4 + ((tid >> 5) & 3)] = ep;
        }
    }
    // ---- U pass: thread (l, sg), 4 samples packed via whiT ----
    {
        int l = tid & 127, sg = tid >> 7;
        int sb = sg * 4;
        ull aU0 = 0ull, aU1 = 0ull;
#pragma unroll 4
        for (int h = 0; h < 128; h++) {
            float pv = sDi[h * 128 + (l ^ ((h & 7) << 2))];
            ull ppv = pk2(pv);
            ulonglong2 w2 = *(const ulonglong2*)(sWhiT + h * 36 + sb);
            aU0 = fma2(ppv, w2.x, aU0);
            aU1 = fma2(ppv, w2.y, aU1);
        }
        float2 u01 = *(float2*)&aU0;
        float2 u23 = *(float2*)&aU1;
        sU[(sb + 0) * 128 + l] = u01.x;
        sU[(sb + 1) * 128 + l] = u01.y;
        sU[(sb + 2) * 128 + l] = u23.x;
        sU[(sb + 3) * 128 + l] = u23.y;
    }
    __syncthreads();

    // ---- finalize: warp w -> sample w (32 warps, 32 samples) ----
    int w = tid >> 5;
    {
        float dacc = 0.f;
        float nh[7] = {0, 0, 0, 0, 0, 0, 0};
        float nl[7] = {0, 0, 0, 0, 0, 0, 0};
        float4 whi4 = *(const float4*)&sWhiS[w * 128 + lane * 4];
        float4 wlo4 = *(const float4*)&sWloS[w * 128 + lane * 4];
        float4 V4   = *(const float4*)&sV[w * 128 + lane * 4];
        float4 U4   = *(const float4*)&sU[w * 128 + lane * 4];
        const float* whiA = (const float*)&whi4;
        const float* wloA = (const float*)&wlo4;
        const float* VA = (const float*)&V4;
        const float* UA = (const float*)&U4;
#pragma unroll
        for (int q = 0; q < 4; q++) {
            int h = lane * 4 + q;
            float wv = whiA[q] * VA[q];
            dacc += wv;
            float wu = wloA[q] * UA[q];
#pragma unroll
            for (int j = 0; j < 7; j++) {
                float bit = (float)((h >> (6 - j)) & 1);
                nh[j] = fmaf(bit, wv, nh[j]);
                nl[j] = fmaf(bit, wu, nl[j]);
            }
        }
#pragma unroll
        for (int m = 16; m >= 1; m >>= 1) {
            dacc += __shfl_xor_sync(0xffffffffu, dacc, m);
#pragma unroll
            for (int j = 0; j < 7; j++) {
                nh[j] += __shfl_xor_sync(0xffffffffu, nh[j], m);
                nl[j] += __shfl_xor_sync(0xffffffffu, nl[j], m);
            }
        }
        if (lane == 0) {
            int c = sc[w];
            float eii = sEiiP[w * 4 + 0] + sEiiP[w * 4 + 1]
                      + sEiiP[w * 4 + 2] + sEiiP[w * 4 + 3];
            float inv = 1.f / dacc;
            float contrib = beta0[c] - eii * inv;
#pragma unroll
            for (int j = 0; j < 7; j++) {
                float Ez = nh[j] * inv;
                contrib += (2.f * Ez - 1.f) * beta[c * M_N + j]
                         + Ez * sle[w * M_N + j];
            }
#pragma unroll
            for (int j = 7; j < 14; j++) {
                float Ez = nl[j - 7] * inv;
                contrib += (2.f * Ez - 1.f) * beta[c * M_N + j]
                         + Ez * sle[w * M_N + j];
            }
            scontrib[w] = contrib;
        }
    }
    __syncthreads();
    if (tid == 0) {
        float t = 0.f;
#pragma unroll
        for (int s = 0; s < SMP; s++) t += scontrib[s];
#pragma unroll
        for (int q = 0; q < 14; q++) t -= sspw[q];   // -EIV
        atomicAdd(&g_acc, (double)t);
    }
}

__global__ void k_fin(float* out) { out[0] = (float)g_acc; }

extern "C" void kernel_launch(void* const* d_in, const int* in_sizes, int n_in,
                              void* d_out, int out_size) {
    const float* x   = (const float*)d_in[0];
    const int*   y   = (const int*)d_in[1];
    const float* a0  = (const float*)d_in[2];
    const float* al  = (const float*)d_in[3];
    const float* b0  = (const float*)d_in[4];
    const float* be  = (const float*)d_in[5];
    float* out = (float*)d_out;

    const int SMEM4 = (16384 * 2 + 4096 * 4 + 4608 + 896 + 448) * 4;  // ~215KB
    cudaFuncSetAttribute(k_main, cudaFuncAttributeMaxDynamicSharedMemorySize, SMEM4);

    k_ehilo<<<C_N, 256>>>(b0, be);
    k_D<<<128, 128>>>();
    k_gemm<<<B_N / 32, 128>>>(x, al, a0);
    k_main<<<B_N / SMP, 1024, SMEM4>>>(y, b0, be);
    k_fin<<<1, 1>>>(out);
}